// round 11
// baseline (speedup 1.0000x reference)
#include <cuda_runtime.h>
#include <cuda_bf16.h>
#include <cstdint>

#define CB 4
#define CC 64
#define CH 8
#define CL 2048
#define CO 512

#define QK_SCALE 0.35355339059327373f
#define LOG2E    1.4426950408889634f

typedef unsigned long long ull;

// ---------------- bf16x2 exp2 path ----------------
__device__ __forceinline__ uint32_t cvt2bf(float hi, float lo) {
    uint32_t d; asm("cvt.rn.bf16x2.f32 %0, %1, %2;" : "=r"(d) : "f"(hi), "f"(lo)); return d;
}
__device__ __forceinline__ uint32_t ex2bf2(uint32_t x) {
    uint32_t d; asm("ex2.approx.ftz.bf16x2 %0, %1;" : "=r"(d) : "r"(x)); return d;
}
#define ONESBF 0x3F803F80u

__device__ __forceinline__ float tf32rna(float x) {
    uint32_t d; asm("cvt.rna.tf32.f32 %0, %1;" : "=r"(d) : "f"(x));
    return __uint_as_float(d);
}

// ---------------- cp.async ----------------
__device__ __forceinline__ void cpa16(uint32_t s, const void* g) {
    asm volatile("cp.async.cg.shared.global [%0], [%1], 16;" :: "r"(s), "l"(g));
}
#define CP_COMMIT() asm volatile("cp.async.commit_group;" ::: "memory")
#define CP_WAIT(n)  asm volatile("cp.async.wait_group %0;" :: "n"(n) : "memory")

__device__ __forceinline__ uint32_t smem_u32(const void* p) {
    uint32_t a;
    asm("{ .reg .u64 t; cvta.to.shared.u64 t, %1; cvt.u32.u64 %0, t; }" : "=r"(a) : "l"(p));
    return a;
}

// ---------------- HMMA m16n8k16 bf16 ----------------
__device__ __forceinline__ void hmma(float* c,
                                     uint32_t a0, uint32_t a1, uint32_t a2, uint32_t a3,
                                     uint32_t b0, uint32_t b1) {
    asm volatile(
        "mma.sync.aligned.m16n8k16.row.col.f32.bf16.bf16.f32 "
        "{%0,%1,%2,%3},{%4,%5,%6,%7},{%8,%9},{%0,%1,%2,%3};"
        : "+f"(c[0]), "+f"(c[1]), "+f"(c[2]), "+f"(c[3])
        : "r"(a0), "r"(a1), "r"(a2), "r"(a3), "r"(b0), "r"(b1));
}
__device__ __forceinline__ void hmma_z(float* d,
                                       uint32_t a0, uint32_t a1, uint32_t a2, uint32_t a3,
                                       uint32_t b0, uint32_t b1) {
    asm volatile(
        "mma.sync.aligned.m16n8k16.row.col.f32.bf16.bf16.f32 "
        "{%0,%1,%2,%3},{%4,%5,%6,%7},{%8,%9},{%10,%11,%12,%13};"
        : "=f"(d[0]), "=f"(d[1]), "=f"(d[2]), "=f"(d[3])
        : "r"(a0), "r"(a1), "r"(a2), "r"(a3), "r"(b0), "r"(b1),
          "f"(0.f), "f"(0.f), "f"(0.f), "f"(0.f));
}

// ---------------- HMMA m16n8k8 tf32 ----------------
__device__ __forceinline__ void tmma(float* c,
                                     uint32_t a0, uint32_t a1, uint32_t a2, uint32_t a3,
                                     uint32_t b0, uint32_t b1) {
    asm volatile(
        "mma.sync.aligned.m16n8k8.row.col.f32.tf32.tf32.f32 "
        "{%0,%1,%2,%3},{%4,%5,%6,%7},{%8,%9},{%0,%1,%2,%3};"
        : "+f"(c[0]), "+f"(c[1]), "+f"(c[2]), "+f"(c[3])
        : "r"(a0), "r"(a1), "r"(a2), "r"(a3), "r"(b0), "r"(b1));
}

__device__ __forceinline__ void ldsm4(uint32_t a, uint32_t& r0, uint32_t& r1,
                                      uint32_t& r2, uint32_t& r3) {
    asm volatile("ldmatrix.sync.aligned.m8n8.x4.shared.b16 {%0,%1,%2,%3}, [%4];"
        : "=r"(r0), "=r"(r1), "=r"(r2), "=r"(r3) : "r"(a));
}

// ---------------- scratch ----------------
__device__ __nv_bfloat16 g_qt[CB * CH * CL * CC];   // [bh][l][c]  (q prescaled)
__device__ __nv_bfloat16 g_kt[CB * CH * CL * CC];   // [bh][l][c]
__device__ __nv_bfloat16 g_vv[CB * CH * CC * CL];   // [bh][d][l]
__device__ float g_att[2 * CB * CO * CL];           // raw partial O, per split
__device__ float g_rs[2 * CB * CH * CL];            // partial rowsums, per split
__device__ __nv_bfloat16 g_w[3 * CO * CC];          // preconverted pw (scales folded)
__device__ float g_uwt[CC * CO];                    // u_w rounded to tf32 (rna)

// ============================================================================
// Prep
// ============================================================================
__global__ __launch_bounds__(256) void prep_kernel(
    const float* __restrict__ qpw, const float* __restrict__ kpw,
    const float* __restrict__ vpw, const float* __restrict__ uw)
{
    int i = blockIdx.x * 256 + threadIdx.x;
    if (i < 24576) {
        int var = i / 8192;
        int off = (i - var * 8192) * 4;
        const float* src = (var == 0) ? qpw : (var == 1) ? kpw : vpw;
        float s = (var == 0) ? QK_SCALE * LOG2E : (var == 1) ? QK_SCALE : 1.0f;
        float4 wv = *(const float4*)&src[off];
        __nv_bfloat162 h0 = __floats2bfloat162_rn(wv.x * s, wv.y * s);
        __nv_bfloat162 h1 = __floats2bfloat162_rn(wv.z * s, wv.w * s);
        *(uint2*)&g_w[var * (CO * CC) + off] = make_uint2(*(uint32_t*)&h0, *(uint32_t*)&h1);
    } else {
        int off = (i - 24576) * 4;
        float4 wv = *(const float4*)&uw[off];
        wv.x = tf32rna(wv.x); wv.y = tf32rna(wv.y);
        wv.z = tf32rna(wv.z); wv.w = tf32rna(wv.w);
        *(float4*)&g_uwt[off] = wv;
    }
}

// ============================================================================
// QKV on HMMA (unchanged from round 9/10).
// ============================================================================
#define QKV_SMEM 82944

__global__ void __launch_bounds__(512) qkv_kernel(
    const float* __restrict__ x,
    const float* __restrict__ qdw, const float* __restrict__ qdb,
    const float* __restrict__ qpb,
    const float* __restrict__ kdw, const float* __restrict__ kdb,
    const float* __restrict__ kpb,
    const float* __restrict__ vdw, const float* __restrict__ vdb,
    const float* __restrict__ vpb)
{
    extern __shared__ char qsm[];
    __nv_bfloat16* ysb = (__nv_bfloat16*)qsm;            // [64 l][72 c]
    __nv_bfloat16* wsb = (__nv_bfloat16*)(qsm + 9216);   // [512 o][72 c]
    uint32_t sb = smem_u32(qsm);

    int var = blockIdx.z;
    const float* dw = (var == 0) ? qdw : (var == 1) ? kdw : vdw;
    const float* db = (var == 0) ? qdb : (var == 1) ? kdb : vdb;
    const float* pb = (var == 0) ? qpb : (var == 1) ? kpb : vpb;
    float bscale   = (var == 0) ? QK_SCALE * LOG2E : (var == 1) ? QK_SCALE : 1.0f;

    int l0 = blockIdx.x * 64;
    int b  = blockIdx.y;
    int tid = threadIdx.x;
    int w = tid >> 5, ln = tid & 31, gp = ln >> 2, tg = ln & 3;
    int head = w >> 1, lh = w & 1;

    const __nv_bfloat16* wg = g_w + (size_t)var * (CO * CC);
    for (int i = tid; i < 4096; i += 512) {
        int r = i >> 3, j = i & 7;
        cpa16(sb + 9216 + r * 144 + j * 16, wg + (size_t)r * CC + j * 8);
    }
    CP_COMMIT();

    for (int idx = tid; idx < 64 * 64; idx += 512) {
        int c = idx >> 6, li = idx & 63;
        int l = l0 + li;
        const float* xr = x + (size_t)(b * CC + c) * CL;
        float w0 = dw[c * 3 + 0], w1 = dw[c * 3 + 1], w2 = dw[c * 3 + 2];
        float xm = (l > 0)      ? xr[l - 1] : 0.f;
        float x0 = xr[l];
        float xp = (l < CL - 1) ? xr[l + 1] : 0.f;
        ysb[li * 72 + c] = __float2bfloat16(db[c] + w0 * xm + w1 * x0 + w2 * xp);
    }
    CP_WAIT(0);
    __syncthreads();

    int obase = head * 64;
    float pbv[4][2];
    #pragma unroll
    for (int mt = 0; mt < 4; mt++) {
        pbv[mt][0] = pb[obase + mt * 16 + gp] * bscale;
        pbv[mt][1] = pb[obase + mt * 16 + gp + 8] * bscale;
    }

    float acc[4][4][4];
    #pragma unroll
    for (int mt = 0; mt < 4; mt++)
        #pragma unroll
        for (int n = 0; n < 4; n++)
            #pragma unroll
            for (int r = 0; r < 4; r++) acc[mt][n][r] = 0.f;

    #pragma unroll
    for (int ks = 0; ks < 4; ks++) {
        uint32_t af[4][4];
        #pragma unroll
        for (int mt = 0; mt < 4; mt++) {
            int row = obase + mt * 16 + gp;
            int col = ks * 16 + tg * 2;
            af[mt][0] = *(const uint32_t*)&wsb[(row)     * 72 + col];
            af[mt][1] = *(const uint32_t*)&wsb[(row + 8) * 72 + col];
            af[mt][2] = *(const uint32_t*)&wsb[(row)     * 72 + col + 8];
            af[mt][3] = *(const uint32_t*)&wsb[(row + 8) * 72 + col + 8];
        }
        #pragma unroll
        for (int n = 0; n < 4; n++) {
            int nrow = lh * 32 + n * 8 + gp, ncol = ks * 16 + tg * 2;
            uint32_t b0 = *(const uint32_t*)&ysb[nrow * 72 + ncol];
            uint32_t b1 = *(const uint32_t*)&ysb[nrow * 72 + ncol + 8];
            #pragma unroll
            for (int mt = 0; mt < 4; mt++)
                hmma(acc[mt][n], af[mt][0], af[mt][1], af[mt][2], af[mt][3], b0, b1);
        }
    }

    __syncthreads();

    __nv_bfloat16* stg = wsb + head * 4608;   // [64][72]
    if (var == 2) {
        #pragma unroll
        for (int mt = 0; mt < 4; mt++)
            #pragma unroll
            for (int n = 0; n < 4; n++) {
                int d = mt * 16 + gp, lcol = lh * 32 + n * 8 + tg * 2;
                __nv_bfloat162 h0 = __floats2bfloat162_rn(acc[mt][n][0] + pbv[mt][0],
                                                          acc[mt][n][1] + pbv[mt][0]);
                __nv_bfloat162 h1 = __floats2bfloat162_rn(acc[mt][n][2] + pbv[mt][1],
                                                          acc[mt][n][3] + pbv[mt][1]);
                *(uint32_t*)&stg[(d)     * 72 + lcol] = *(uint32_t*)&h0;
                *(uint32_t*)&stg[(d + 8) * 72 + lcol] = *(uint32_t*)&h1;
            }
    } else {
        #pragma unroll
        for (int mt = 0; mt < 4; mt++)
            #pragma unroll
            for (int n = 0; n < 4; n++) {
                int d = mt * 16 + gp, lcol = lh * 32 + n * 8 + tg * 2;
                stg[(lcol)     * 72 + d]     = __float2bfloat16(acc[mt][n][0] + pbv[mt][0]);
                stg[(lcol + 1) * 72 + d]     = __float2bfloat16(acc[mt][n][1] + pbv[mt][0]);
                stg[(lcol)     * 72 + d + 8] = __float2bfloat16(acc[mt][n][2] + pbv[mt][1]);
                stg[(lcol + 1) * 72 + d + 8] = __float2bfloat16(acc[mt][n][3] + pbv[mt][1]);
            }
    }
    __syncthreads();

    int bh = b * CH + head;
    int lane64 = lh * 32 + ln;
    if (var == 2) {
        for (int i = lane64; i < 512; i += 64) {
            int r = i >> 3, j = i & 7;
            *(uint4*)&g_vv[((size_t)(bh * CC + r)) * CL + l0 + j * 8] =
                *(const uint4*)&stg[r * 72 + j * 8];
        }
    } else {
        __nv_bfloat16* outp = (var == 0) ? g_qt : g_kt;
        for (int i = lane64; i < 512; i += 64) {
            int r = i >> 3, j = i & 7;
            *(uint4*)&outp[((size_t)bh * CL + l0 + r) * CC + j * 8] =
                *(const uint4*)&stg[r * 72 + j * 8];
        }
    }
}

// ============================================================================
// Flash attention, split-K=2, 256 threads (8 warps x 16 queries), occupancy 2.
// ============================================================================
#define KT      64
#define NT      (CL / KT / 2)   // 16 tiles per split
#define KV_OFF  18432
#define KV_STR  18432
#define FL_SMEM 55296

__global__ void __launch_bounds__(256, 2) flash_kernel()
{
    extern __shared__ char sm[];
    uint32_t sb = smem_u32(sm);
    float* Osm = (float*)sm;

    int tid = threadIdx.x;
    int w   = tid >> 5;          // 0..7, warp owns q rows [w*16, w*16+16)
    int ln  = tid & 31;
    int gp  = ln >> 2;
    int tg  = ln & 3;
    int l0  = blockIdx.x * 128;
    int s   = blockIdx.z & 1;
    int bh  = (blockIdx.z >> 1) * CH + blockIdx.y;
    int kbase0 = s * (CL / 2);

    int t4 = ln >> 3;
    uint32_t lk  = (((t4 >> 1) * 8 + (ln & 7)) * 144) + ((t4 & 1) * 16);
    uint32_t qlk = (((t4 & 1) * 8 + (ln & 7)) * 144) + ((t4 >> 1) * 16);
    uint32_t qwarp = sb + (uint32_t)(w * 16) * 144 + qlk;

    const __nv_bfloat16* qg = g_qt + (size_t)bh * CL * CC;
    const __nv_bfloat16* kg = g_kt + (size_t)bh * CL * CC;
    const __nv_bfloat16* vg = g_vv + (size_t)bh * CC * CL;

    for (int c = tid; c < 1024; c += 256) {
        int r = c >> 3, j = c & 7;
        cpa16(sb + r * 144 + j * 16, qg + ((size_t)(l0 + r)) * CC + j * 8);
    }
    for (int c = tid; c < 512; c += 256) {
        int r = c >> 3, j = c & 7;
        cpa16(sb + KV_OFF + r * 144 + j * 16, kg + ((size_t)(kbase0 + r)) * CC + j * 8);
        cpa16(sb + KV_OFF + 9216 + r * 144 + j * 16, vg + (size_t)r * CL + kbase0 + j * 8);
    }
    CP_COMMIT();
    CP_WAIT(0);
    __syncthreads();

    float Oacc[8][4];
    #pragma unroll
    for (int n = 0; n < 8; n++)
        #pragma unroll
        for (int r = 0; r < 4; r++) Oacc[n][r] = 0.f;
    float Racc[4];
    #pragma unroll
    for (int r = 0; r < 4; r++) Racc[r] = 0.f;

    for (int i = 0; i < NT; i++) {
        if (i > 0) CP_WAIT(0);
        __syncthreads();

        if (i + 1 < NT) {
            int n0 = kbase0 + (i + 1) * KT;
            uint32_t base = sb + KV_OFF + ((i + 1) & 1) * KV_STR;
            for (int c = tid; c < 512; c += 256) {
                int r = c >> 3, j = c & 7;
                cpa16(base + r * 144 + j * 16, kg + ((size_t)(n0 + r)) * CC + j * 8);
                cpa16(base + 9216 + r * 144 + j * 16, vg + (size_t)r * CL + n0 + j * 8);
            }
            CP_COMMIT();
        }

        uint32_t kb = sb + KV_OFF + (i & 1) * KV_STR + lk;
        uint32_t vb = kb + 9216;

        float Sacc[8][4];

        // ---- MMA1: S = Q . K^T ----
        #pragma unroll
        for (int ks = 0; ks < 4; ks++) {
            uint32_t q0, q1, q2, q3;
            ldsm4(qwarp + ks * 32, q0, q1, q2, q3);
            #pragma unroll
            for (int ng2 = 0; ng2 < 4; ng2++) {
                uint32_t k0, k1, k2, k3;
                ldsm4(kb + ng2 * 2304 + ks * 32, k0, k1, k2, k3);
                if (ks == 0) {
                    hmma_z(Sacc[2 * ng2],     q0, q1, q2, q3, k0, k1);
                    hmma_z(Sacc[2 * ng2 + 1], q0, q1, q2, q3, k2, k3);
                } else {
                    hmma(Sacc[2 * ng2],     q0, q1, q2, q3, k0, k1);
                    hmma(Sacc[2 * ng2 + 1], q0, q1, q2, q3, k2, k3);
                }
            }
        }

        // ---- P = ex2(S); O += P.V; rowsum += P.ones ----
        #pragma unroll
        for (int ks = 0; ks < 4; ks++) {
            uint32_t pa0 = ex2bf2(cvt2bf(Sacc[2 * ks][1],     Sacc[2 * ks][0]));
            uint32_t pa1 = ex2bf2(cvt2bf(Sacc[2 * ks][3],     Sacc[2 * ks][2]));
            uint32_t pa2 = ex2bf2(cvt2bf(Sacc[2 * ks + 1][1], Sacc[2 * ks + 1][0]));
            uint32_t pa3 = ex2bf2(cvt2bf(Sacc[2 * ks + 1][3], Sacc[2 * ks + 1][2]));
            #pragma unroll
            for (int ng2 = 0; ng2 < 4; ng2++) {
                uint32_t v0, v1, v2, v3;
                ldsm4(vb + ng2 * 2304 + ks * 32, v0, v1, v2, v3);
                hmma(Oacc[2 * ng2],     pa0, pa1, pa2, pa3, v0, v1);
                hmma(Oacc[2 * ng2 + 1], pa0, pa1, pa2, pa3, v2, v3);
            }
            hmma(Racc, pa0, pa1, pa2, pa3, ONESBF, ONESBF);
        }
    }

    // partial rowsums
    float* rsb = g_rs + (size_t)s * (CB * CH * CL) + (size_t)bh * CL + l0;
    if (tg == 0) {
        rsb[w * 16 + gp]     = Racc[0];
        rsb[w * 16 + gp + 8] = Racc[2];
    }

    __syncthreads();
    {
        int qb = w * 16 + gp;
        #pragma unroll
        for (int n = 0; n < 8; n++) {
            int d = n * 8 + tg * 2;
            Osm[(d)     * 132 + qb]     = Oacc[n][0];
            Osm[(d + 1) * 132 + qb]     = Oacc[n][1];
            Osm[(d)     * 132 + qb + 8] = Oacc[n][2];
            Osm[(d + 1) * 132 + qb + 8] = Oacc[n][3];
        }
    }
    __syncthreads();

    float* ob = g_att + (size_t)s * (CB * CO * CL) + (size_t)bh * CC * CL + l0;
    for (int c = tid; c < 2048; c += 256) {
        int d = c >> 5, q4 = (c & 31) << 2;
        *(float4*)&ob[(size_t)d * CL + q4] = *(const float4*)&Osm[d * 132 + q4];
    }
}

// ============================================================================
// Unify heads on tf32 HMMA; l-tile 32, grid 256 CTAs, occupancy 2.
// Buf slot: O0 [64 o][36 l] @0 (9216B), O1 @9216, W [64 c][68 o] @18432 (17408B).
// ============================================================================
#define UB_STR  35840
#define U_SMEM  (3 * UB_STR)

__global__ void __launch_bounds__(256, 2) unify_kernel(
    const float* __restrict__ ub, float* __restrict__ y)
{
    extern __shared__ float usm[];
    uint32_t sbU = smem_u32(usm);

    int tid = threadIdx.x;
    int w = tid >> 5, ln = tid & 31, gp = ln >> 2, tg = ln & 3;
    int wm = w & 3, wn = w >> 2;   // wm: 16-c row group; wn: 16-l col group (0..1)
    int l0 = blockIdx.x * 32, b = blockIdx.y;

    auto issue = [&](int t) {
        uint32_t base = sbU + (t % 3) * UB_STR;
        const float* a0g = g_att + (size_t)(b * CO + t * 64) * CL + l0;
        const float* a1g = a0g + (size_t)CB * CO * CL;
        for (int i = tid; i < 512; i += 256) {
            int o = i >> 3, j = i & 7;
            cpa16(base + o * 144 + j * 16, a0g + (size_t)o * CL + j * 4);
            cpa16(base + 9216 + o * 144 + j * 16, a1g + (size_t)o * CL + j * 4);
        }
        const float* wg = g_uwt + t * 64;
        for (int i = tid; i < 1024; i += 256) {
            int c = i >> 4, j = i & 15;
            cpa16(base + 18432 + c * 272 + j * 16, wg + (size_t)c * CO + j * 4);
        }
        CP_COMMIT();
    };

    issue(0);
    issue(1);

    float acc[2][4];
    #pragma unroll
    for (int ns = 0; ns < 2; ns++)
        #pragma unroll
        for (int r = 0; r < 4; r++) acc[ns][r] = 0.f;

    for (int t = 0; t < 8; t++) {
        if (t < 7) { CP_WAIT(1); } else { CP_WAIT(0); }
        __syncthreads();
        if (t + 2 < 8) issue(t + 2);

        float* O0 = usm + (t % 3) * (UB_STR / 4);   // [o][36 l]
        const float* O1 = O0 + 2304;
        const float* Aw = O0 + 4608;                // [c][68 o]

        // combine: att = (O0 + O1) / (rs0 + rs1), rna; in place into O0
        {
            int lcol = tid & 31, og = tid >> 5;
            const float* rs0 = g_rs + (size_t)(b * CH + t) * CL + l0;
            float inv = 1.0f / (rs0[lcol] + rs0[(size_t)CB * CH * CL + lcol]);
            #pragma unroll
            for (int k = 0; k < 8; k++) {
                int o = og * 8 + k;
                O0[o * 36 + lcol] = tf32rna((O0[o * 36 + lcol] + O1[o * 36 + lcol]) * inv);
            }
        }
        __syncthreads();

        #pragma unroll
        for (int ks = 0; ks < 8; ks++) {
            int k0 = ks * 8;
            int ra = (wm * 16 + gp) * 68 + k0;
            uint32_t a0 = *(const uint32_t*)&Aw[ra + tg];
            uint32_t a1 = *(const uint32_t*)&Aw[ra + 8 * 68 + tg];
            uint32_t a2 = *(const uint32_t*)&Aw[ra + tg + 4];
            uint32_t a3 = *(const uint32_t*)&Aw[ra + 8 * 68 + tg + 4];
            int rb0 = (k0 + tg) * 36 + wn * 16 + gp;
            int rb1 = (k0 + tg + 4) * 36 + wn * 16 + gp;
            #pragma unroll
            for (int ns = 0; ns < 2; ns++) {
                uint32_t b0 = *(const uint32_t*)&O0[rb0 + ns * 8];
                uint32_t b1 = *(const uint32_t*)&O0[rb1 + ns * 8];
                tmma(acc[ns], a0, a1, a2, a3, b0, b1);
            }
        }
    }

    __syncthreads();
    float* stg = usm;   // [64 c][36 l]
    #pragma unroll
    for (int ns = 0; ns < 2; ns++) {
        int lcol = wn * 16 + ns * 8 + tg * 2;
        int c = wm * 16 + gp;
        *(float2*)&stg[(c)     * 36 + lcol] = make_float2(acc[ns][0], acc[ns][1]);
        *(float2*)&stg[(c + 8) * 36 + lcol] = make_float2(acc[ns][2], acc[ns][3]);
    }
    __syncthreads();

    for (int i = tid; i < 512; i += 256) {
        int c = i >> 3, l4 = (i & 7) << 2;
        float bb = ub[c];
        float4 v = *(const float4*)&stg[c * 36 + l4];
        v.x += bb; v.y += bb; v.z += bb; v.w += bb;
        *(float4*)&y[(size_t)(b * CC + c) * CL + l0 + l4] = v;
    }
}

// ============================================================================
extern "C" void kernel_launch(void* const* d_in, const int* in_sizes, int n_in,
                              void* d_out, int out_size)
{
    (void)in_sizes; (void)n_in; (void)out_size;
    const float* x    = (const float*)d_in[0];
    const float* q_dw = (const float*)d_in[1];
    const float* q_db = (const float*)d_in[2];
    const float* q_pw = (const float*)d_in[3];
    const float* q_pb = (const float*)d_in[4];
    const float* k_dw = (const float*)d_in[5];
    const float* k_db = (const float*)d_in[6];
    const float* k_pw = (const float*)d_in[7];
    const float* k_pb = (const float*)d_in[8];
    const float* v_dw = (const float*)d_in[9];
    const float* v_db = (const float*)d_in[10];
    const float* v_pw = (const float*)d_in[11];
    const float* v_pb = (const float*)d_in[12];
    const float* u_w  = (const float*)d_in[13];
    const float* u_b  = (const float*)d_in[14];

    cudaFuncSetAttribute(qkv_kernel,
                         cudaFuncAttributeMaxDynamicSharedMemorySize, QKV_SMEM);
    cudaFuncSetAttribute(flash_kernel,
                         cudaFuncAttributeMaxDynamicSharedMemorySize, FL_SMEM);
    cudaFuncSetAttribute(unify_kernel,
                         cudaFuncAttributeMaxDynamicSharedMemorySize, U_SMEM);

    prep_kernel<<<128, 256>>>(q_pw, k_pw, v_pw, u_w);

    qkv_kernel<<<dim3(CL / 64, CB, 3), 512, QKV_SMEM>>>(
        x, q_dw, q_db, q_pb, k_dw, k_db, k_pb, v_dw, v_db, v_pb);

    flash_kernel<<<dim3(CL / 128, CH, CB * 2), 256, FL_SMEM>>>();

    unify_kernel<<<dim3(CL / 32, CB), 256, U_SMEM>>>(u_b, (float*)d_out);
}

// round 12
// speedup vs baseline: 1.0290x; 1.0290x over previous
#include <cuda_runtime.h>
#include <cuda_bf16.h>
#include <cstdint>

#define CB 4
#define CC 64
#define CH 8
#define CL 2048
#define CO 512

#define QK_SCALE 0.35355339059327373f
#define LOG2E    1.4426950408889634f

typedef unsigned long long ull;

// ---------------- bf16x2 exp2 path ----------------
__device__ __forceinline__ uint32_t cvt2bf(float hi, float lo) {
    uint32_t d; asm("cvt.rn.bf16x2.f32 %0, %1, %2;" : "=r"(d) : "f"(hi), "f"(lo)); return d;
}
__device__ __forceinline__ uint32_t ex2bf2(uint32_t x) {
    uint32_t d; asm("ex2.approx.ftz.bf16x2 %0, %1;" : "=r"(d) : "r"(x)); return d;
}
#define ONESBF 0x3F803F80u

__device__ __forceinline__ float tf32rna(float x) {
    uint32_t d; asm("cvt.rna.tf32.f32 %0, %1;" : "=r"(d) : "f"(x));
    return __uint_as_float(d);
}

// ---------------- cp.async / redg ----------------
__device__ __forceinline__ void cpa16(uint32_t s, const void* g) {
    asm volatile("cp.async.cg.shared.global [%0], [%1], 16;" :: "r"(s), "l"(g));
}
#define CP_COMMIT() asm volatile("cp.async.commit_group;" ::: "memory")
#define CP_WAIT(n)  asm volatile("cp.async.wait_group %0;" :: "n"(n) : "memory")

__device__ __forceinline__ void redadd(float* p, float v) {
    asm volatile("red.global.add.f32 [%0], %1;" :: "l"(p), "f"(v) : "memory");
}

__device__ __forceinline__ uint32_t smem_u32(const void* p) {
    uint32_t a;
    asm("{ .reg .u64 t; cvta.to.shared.u64 t, %1; cvt.u32.u64 %0, t; }" : "=r"(a) : "l"(p));
    return a;
}

// ---------------- HMMA m16n8k16 bf16 ----------------
__device__ __forceinline__ void hmma(float* c,
                                     uint32_t a0, uint32_t a1, uint32_t a2, uint32_t a3,
                                     uint32_t b0, uint32_t b1) {
    asm volatile(
        "mma.sync.aligned.m16n8k16.row.col.f32.bf16.bf16.f32 "
        "{%0,%1,%2,%3},{%4,%5,%6,%7},{%8,%9},{%0,%1,%2,%3};"
        : "+f"(c[0]), "+f"(c[1]), "+f"(c[2]), "+f"(c[3])
        : "r"(a0), "r"(a1), "r"(a2), "r"(a3), "r"(b0), "r"(b1));
}
__device__ __forceinline__ void hmma_z(float* d,
                                       uint32_t a0, uint32_t a1, uint32_t a2, uint32_t a3,
                                       uint32_t b0, uint32_t b1) {
    asm volatile(
        "mma.sync.aligned.m16n8k16.row.col.f32.bf16.bf16.f32 "
        "{%0,%1,%2,%3},{%4,%5,%6,%7},{%8,%9},{%10,%11,%12,%13};"
        : "=f"(d[0]), "=f"(d[1]), "=f"(d[2]), "=f"(d[3])
        : "r"(a0), "r"(a1), "r"(a2), "r"(a3), "r"(b0), "r"(b1),
          "f"(0.f), "f"(0.f), "f"(0.f), "f"(0.f));
}

// ---------------- HMMA m16n8k8 tf32 ----------------
__device__ __forceinline__ void tmma(float* c,
                                     uint32_t a0, uint32_t a1, uint32_t a2, uint32_t a3,
                                     uint32_t b0, uint32_t b1) {
    asm volatile(
        "mma.sync.aligned.m16n8k8.row.col.f32.tf32.tf32.f32 "
        "{%0,%1,%2,%3},{%4,%5,%6,%7},{%8,%9},{%0,%1,%2,%3};"
        : "+f"(c[0]), "+f"(c[1]), "+f"(c[2]), "+f"(c[3])
        : "r"(a0), "r"(a1), "r"(a2), "r"(a3), "r"(b0), "r"(b1));
}

__device__ __forceinline__ void ldsm4(uint32_t a, uint32_t& r0, uint32_t& r1,
                                      uint32_t& r2, uint32_t& r3) {
    asm volatile("ldmatrix.sync.aligned.m8n8.x4.shared.b16 {%0,%1,%2,%3}, [%4];"
        : "=r"(r0), "=r"(r1), "=r"(r2), "=r"(r3) : "r"(a));
}

// ---------------- scratch ----------------
__device__ __nv_bfloat16 g_qt[CB * CH * CL * CC];   // [bh][l][c]  (q prescaled)
__device__ __nv_bfloat16 g_kt[CB * CH * CL * CC];   // [bh][l][c]
__device__ __nv_bfloat16 g_vv[CB * CH * CC * CL];   // [bh][d][l]
__device__ float g_att[CB * CO * CL];               // summed raw O (REDG target)
__device__ float g_rs[CB * CH * CL];                // summed rowsums (REDG target)
__device__ __nv_bfloat16 g_w[3 * CO * CC];          // preconverted pw (scales folded)
__device__ float g_uwt[CC * CO];                    // u_w rounded to tf32 (rna)

// ============================================================================
// Zero: clear REDG targets every launch (graph-replayed).
// ============================================================================
#define NZ_ATT (CB * CO * CL / 4)   // 1048576 float4
#define NZ_RS  (CB * CH * CL / 4)   // 16384 float4
#define NZ_GRID ((NZ_ATT + NZ_RS) / 256)

__global__ __launch_bounds__(256) void zero_kernel()
{
    size_t i = (size_t)blockIdx.x * 256 + threadIdx.x;
    float4 z = make_float4(0.f, 0.f, 0.f, 0.f);
    if (i < NZ_ATT) *(float4*)&g_att[i * 4] = z;
    else            *(float4*)&g_rs[(i - NZ_ATT) * 4] = z;
}

// ============================================================================
// Prep
// ============================================================================
__global__ __launch_bounds__(256) void prep_kernel(
    const float* __restrict__ qpw, const float* __restrict__ kpw,
    const float* __restrict__ vpw, const float* __restrict__ uw)
{
    int i = blockIdx.x * 256 + threadIdx.x;
    if (i < 24576) {
        int var = i / 8192;
        int off = (i - var * 8192) * 4;
        const float* src = (var == 0) ? qpw : (var == 1) ? kpw : vpw;
        float s = (var == 0) ? QK_SCALE * LOG2E : (var == 1) ? QK_SCALE : 1.0f;
        float4 wv = *(const float4*)&src[off];
        __nv_bfloat162 h0 = __floats2bfloat162_rn(wv.x * s, wv.y * s);
        __nv_bfloat162 h1 = __floats2bfloat162_rn(wv.z * s, wv.w * s);
        *(uint2*)&g_w[var * (CO * CC) + off] = make_uint2(*(uint32_t*)&h0, *(uint32_t*)&h1);
    } else {
        int off = (i - 24576) * 4;
        float4 wv = *(const float4*)&uw[off];
        wv.x = tf32rna(wv.x); wv.y = tf32rna(wv.y);
        wv.z = tf32rna(wv.z); wv.w = tf32rna(wv.w);
        *(float4*)&g_uwt[off] = wv;
    }
}

// ============================================================================
// QKV on HMMA (unchanged).
// ============================================================================
#define QKV_SMEM 82944

__global__ void __launch_bounds__(512) qkv_kernel(
    const float* __restrict__ x,
    const float* __restrict__ qdw, const float* __restrict__ qdb,
    const float* __restrict__ qpb,
    const float* __restrict__ kdw, const float* __restrict__ kdb,
    const float* __restrict__ kpb,
    const float* __restrict__ vdw, const float* __restrict__ vdb,
    const float* __restrict__ vpb)
{
    extern __shared__ char qsm[];
    __nv_bfloat16* ysb = (__nv_bfloat16*)qsm;            // [64 l][72 c]
    __nv_bfloat16* wsb = (__nv_bfloat16*)(qsm + 9216);   // [512 o][72 c]
    uint32_t sb = smem_u32(qsm);

    int var = blockIdx.z;
    const float* dw = (var == 0) ? qdw : (var == 1) ? kdw : vdw;
    const float* db = (var == 0) ? qdb : (var == 1) ? kdb : vdb;
    const float* pb = (var == 0) ? qpb : (var == 1) ? kpb : vpb;
    float bscale   = (var == 0) ? QK_SCALE * LOG2E : (var == 1) ? QK_SCALE : 1.0f;

    int l0 = blockIdx.x * 64;
    int b  = blockIdx.y;
    int tid = threadIdx.x;
    int w = tid >> 5, ln = tid & 31, gp = ln >> 2, tg = ln & 3;
    int head = w >> 1, lh = w & 1;

    const __nv_bfloat16* wg = g_w + (size_t)var * (CO * CC);
    for (int i = tid; i < 4096; i += 512) {
        int r = i >> 3, j = i & 7;
        cpa16(sb + 9216 + r * 144 + j * 16, wg + (size_t)r * CC + j * 8);
    }
    CP_COMMIT();

    for (int idx = tid; idx < 64 * 64; idx += 512) {
        int c = idx >> 6, li = idx & 63;
        int l = l0 + li;
        const float* xr = x + (size_t)(b * CC + c) * CL;
        float w0 = dw[c * 3 + 0], w1 = dw[c * 3 + 1], w2 = dw[c * 3 + 2];
        float xm = (l > 0)      ? xr[l - 1] : 0.f;
        float x0 = xr[l];
        float xp = (l < CL - 1) ? xr[l + 1] : 0.f;
        ysb[li * 72 + c] = __float2bfloat16(db[c] + w0 * xm + w1 * x0 + w2 * xp);
    }
    CP_WAIT(0);
    __syncthreads();

    int obase = head * 64;
    float pbv[4][2];
    #pragma unroll
    for (int mt = 0; mt < 4; mt++) {
        pbv[mt][0] = pb[obase + mt * 16 + gp] * bscale;
        pbv[mt][1] = pb[obase + mt * 16 + gp + 8] * bscale;
    }

    float acc[4][4][4];
    #pragma unroll
    for (int mt = 0; mt < 4; mt++)
        #pragma unroll
        for (int n = 0; n < 4; n++)
            #pragma unroll
            for (int r = 0; r < 4; r++) acc[mt][n][r] = 0.f;

    #pragma unroll
    for (int ks = 0; ks < 4; ks++) {
        uint32_t af[4][4];
        #pragma unroll
        for (int mt = 0; mt < 4; mt++) {
            int row = obase + mt * 16 + gp;
            int col = ks * 16 + tg * 2;
            af[mt][0] = *(const uint32_t*)&wsb[(row)     * 72 + col];
            af[mt][1] = *(const uint32_t*)&wsb[(row + 8) * 72 + col];
            af[mt][2] = *(const uint32_t*)&wsb[(row)     * 72 + col + 8];
            af[mt][3] = *(const uint32_t*)&wsb[(row + 8) * 72 + col + 8];
        }
        #pragma unroll
        for (int n = 0; n < 4; n++) {
            int nrow = lh * 32 + n * 8 + gp, ncol = ks * 16 + tg * 2;
            uint32_t b0 = *(const uint32_t*)&ysb[nrow * 72 + ncol];
            uint32_t b1 = *(const uint32_t*)&ysb[nrow * 72 + ncol + 8];
            #pragma unroll
            for (int mt = 0; mt < 4; mt++)
                hmma(acc[mt][n], af[mt][0], af[mt][1], af[mt][2], af[mt][3], b0, b1);
        }
    }

    __syncthreads();

    __nv_bfloat16* stg = wsb + head * 4608;   // [64][72]
    if (var == 2) {
        #pragma unroll
        for (int mt = 0; mt < 4; mt++)
            #pragma unroll
            for (int n = 0; n < 4; n++) {
                int d = mt * 16 + gp, lcol = lh * 32 + n * 8 + tg * 2;
                __nv_bfloat162 h0 = __floats2bfloat162_rn(acc[mt][n][0] + pbv[mt][0],
                                                          acc[mt][n][1] + pbv[mt][0]);
                __nv_bfloat162 h1 = __floats2bfloat162_rn(acc[mt][n][2] + pbv[mt][1],
                                                          acc[mt][n][3] + pbv[mt][1]);
                *(uint32_t*)&stg[(d)     * 72 + lcol] = *(uint32_t*)&h0;
                *(uint32_t*)&stg[(d + 8) * 72 + lcol] = *(uint32_t*)&h1;
            }
    } else {
        #pragma unroll
        for (int mt = 0; mt < 4; mt++)
            #pragma unroll
            for (int n = 0; n < 4; n++) {
                int d = mt * 16 + gp, lcol = lh * 32 + n * 8 + tg * 2;
                stg[(lcol)     * 72 + d]     = __float2bfloat16(acc[mt][n][0] + pbv[mt][0]);
                stg[(lcol + 1) * 72 + d]     = __float2bfloat16(acc[mt][n][1] + pbv[mt][0]);
                stg[(lcol)     * 72 + d + 8] = __float2bfloat16(acc[mt][n][2] + pbv[mt][1]);
                stg[(lcol + 1) * 72 + d + 8] = __float2bfloat16(acc[mt][n][3] + pbv[mt][1]);
            }
    }
    __syncthreads();

    int bh = b * CH + head;
    int lane64 = lh * 32 + ln;
    if (var == 2) {
        for (int i = lane64; i < 512; i += 64) {
            int r = i >> 3, j = i & 7;
            *(uint4*)&g_vv[((size_t)(bh * CC + r)) * CL + l0 + j * 8] =
                *(const uint4*)&stg[r * 72 + j * 8];
        }
    } else {
        __nv_bfloat16* outp = (var == 0) ? g_qt : g_kt;
        for (int i = lane64; i < 512; i += 64) {
            int r = i >> 3, j = i & 7;
            *(uint4*)&outp[((size_t)bh * CL + l0 + r) * CC + j * 8] =
                *(const uint4*)&stg[r * 72 + j * 8];
        }
    }
}

// ============================================================================
// Flash attention, split-K=2, 128 threads (round-10 shape), occ 3.
// O + rowsums accumulated into globals via red.global.add (2 adds/addr:
// bitwise-deterministic since fp add of two operands is commutative).
// ============================================================================
#define KT      64
#define NT      (CL / KT / 2)   // 16 tiles per split
#define KV_OFF  18432
#define KV_STR  18432
#define FL_SMEM 55296

__global__ void __launch_bounds__(128, 3) flash_kernel()
{
    extern __shared__ char sm[];
    uint32_t sb = smem_u32(sm);
    float* Osm = (float*)sm;

    int tid = threadIdx.x;
    int w   = tid >> 5;
    int ln  = tid & 31;
    int gp  = ln >> 2;
    int tg  = ln & 3;
    int l0  = blockIdx.x * 128;
    int s   = blockIdx.z & 1;
    int bh  = (blockIdx.z >> 1) * CH + blockIdx.y;
    int kbase0 = s * (CL / 2);

    int t4 = ln >> 3;
    uint32_t lk  = (((t4 >> 1) * 8 + (ln & 7)) * 144) + ((t4 & 1) * 16);
    uint32_t qlk = (((t4 & 1) * 8 + (ln & 7)) * 144) + ((t4 >> 1) * 16);
    uint32_t qwarp = sb + (uint32_t)(w * 32) * 144 + qlk;

    const __nv_bfloat16* qg = g_qt + (size_t)bh * CL * CC;
    const __nv_bfloat16* kg = g_kt + (size_t)bh * CL * CC;
    const __nv_bfloat16* vg = g_vv + (size_t)bh * CC * CL;

    for (int c = tid; c < 1024; c += 128) {
        int r = c >> 3, j = c & 7;
        cpa16(sb + r * 144 + j * 16, qg + ((size_t)(l0 + r)) * CC + j * 8);
    }
    for (int c = tid; c < 512; c += 128) {
        int r = c >> 3, j = c & 7;
        cpa16(sb + KV_OFF + r * 144 + j * 16, kg + ((size_t)(kbase0 + r)) * CC + j * 8);
        cpa16(sb + KV_OFF + 9216 + r * 144 + j * 16, vg + (size_t)r * CL + kbase0 + j * 8);
    }
    CP_COMMIT();
    CP_WAIT(0);
    __syncthreads();

    float Oacc[2][8][4];
    #pragma unroll
    for (int mt = 0; mt < 2; mt++)
        #pragma unroll
        for (int n = 0; n < 8; n++)
            #pragma unroll
            for (int r = 0; r < 4; r++) Oacc[mt][n][r] = 0.f;
    float Racc[2][4];
    #pragma unroll
    for (int mt = 0; mt < 2; mt++)
        #pragma unroll
        for (int r = 0; r < 4; r++) Racc[mt][r] = 0.f;

    for (int i = 0; i < NT; i++) {
        if (i > 0) CP_WAIT(0);
        __syncthreads();

        if (i + 1 < NT) {
            int n0 = kbase0 + (i + 1) * KT;
            uint32_t base = sb + KV_OFF + ((i + 1) & 1) * KV_STR;
            for (int c = tid; c < 512; c += 128) {
                int r = c >> 3, j = c & 7;
                cpa16(base + r * 144 + j * 16, kg + ((size_t)(n0 + r)) * CC + j * 8);
                cpa16(base + 9216 + r * 144 + j * 16, vg + (size_t)r * CL + n0 + j * 8);
            }
            CP_COMMIT();
        }

        uint32_t kb = sb + KV_OFF + (i & 1) * KV_STR + lk;
        uint32_t vb = kb + 9216;

        float Sacc[2][8][4];

        #pragma unroll
        for (int ks = 0; ks < 4; ks++) {
            uint32_t qf[2][4];
            #pragma unroll
            for (int mt = 0; mt < 2; mt++)
                ldsm4(qwarp + (uint32_t)(mt * 16) * 144 + ks * 32,
                      qf[mt][0], qf[mt][1], qf[mt][2], qf[mt][3]);
            #pragma unroll
            for (int ng2 = 0; ng2 < 4; ng2++) {
                uint32_t k0, k1, k2, k3;
                ldsm4(kb + ng2 * 2304 + ks * 32, k0, k1, k2, k3);
                if (ks == 0) {
                    hmma_z(Sacc[0][2 * ng2],     qf[0][0], qf[0][1], qf[0][2], qf[0][3], k0, k1);
                    hmma_z(Sacc[0][2 * ng2 + 1], qf[0][0], qf[0][1], qf[0][2], qf[0][3], k2, k3);
                    hmma_z(Sacc[1][2 * ng2],     qf[1][0], qf[1][1], qf[1][2], qf[1][3], k0, k1);
                    hmma_z(Sacc[1][2 * ng2 + 1], qf[1][0], qf[1][1], qf[1][2], qf[1][3], k2, k3);
                } else {
                    hmma(Sacc[0][2 * ng2],     qf[0][0], qf[0][1], qf[0][2], qf[0][3], k0, k1);
                    hmma(Sacc[0][2 * ng2 + 1], qf[0][0], qf[0][1], qf[0][2], qf[0][3], k2, k3);
                    hmma(Sacc[1][2 * ng2],     qf[1][0], qf[1][1], qf[1][2], qf[1][3], k0, k1);
                    hmma(Sacc[1][2 * ng2 + 1], qf[1][0], qf[1][1], qf[1][2], qf[1][3], k2, k3);
                }
            }
        }

        #pragma unroll
        for (int ks = 0; ks < 4; ks++) {
            uint32_t pa[2][4];
            #pragma unroll
            for (int mt = 0; mt < 2; mt++) {
                pa[mt][0] = ex2bf2(cvt2bf(Sacc[mt][2 * ks][1],     Sacc[mt][2 * ks][0]));
                pa[mt][1] = ex2bf2(cvt2bf(Sacc[mt][2 * ks][3],     Sacc[mt][2 * ks][2]));
                pa[mt][2] = ex2bf2(cvt2bf(Sacc[mt][2 * ks + 1][1], Sacc[mt][2 * ks + 1][0]));
                pa[mt][3] = ex2bf2(cvt2bf(Sacc[mt][2 * ks + 1][3], Sacc[mt][2 * ks + 1][2]));
            }
            #pragma unroll
            for (int ng2 = 0; ng2 < 4; ng2++) {
                uint32_t v0, v1, v2, v3;
                ldsm4(vb + ng2 * 2304 + ks * 32, v0, v1, v2, v3);
                hmma(Oacc[0][2 * ng2],     pa[0][0], pa[0][1], pa[0][2], pa[0][3], v0, v1);
                hmma(Oacc[0][2 * ng2 + 1], pa[0][0], pa[0][1], pa[0][2], pa[0][3], v2, v3);
                hmma(Oacc[1][2 * ng2],     pa[1][0], pa[1][1], pa[1][2], pa[1][3], v0, v1);
                hmma(Oacc[1][2 * ng2 + 1], pa[1][0], pa[1][1], pa[1][2], pa[1][3], v2, v3);
            }
            hmma(Racc[0], pa[0][0], pa[0][1], pa[0][2], pa[0][3], ONESBF, ONESBF);
            hmma(Racc[1], pa[1][0], pa[1][1], pa[1][2], pa[1][3], ONESBF, ONESBF);
        }
    }

    // rowsums: REDG-accumulate across splits
    float* rsb = g_rs + (size_t)bh * CL + l0;
    if (tg == 0) {
        #pragma unroll
        for (int mt = 0; mt < 2; mt++) {
            redadd(&rsb[w * 32 + mt * 16 + gp],     Racc[mt][0]);
            redadd(&rsb[w * 32 + mt * 16 + gp + 8], Racc[mt][2]);
        }
    }

    __syncthreads();
    #pragma unroll
    for (int mt = 0; mt < 2; mt++) {
        int qb = w * 32 + mt * 16 + gp;
        #pragma unroll
        for (int n = 0; n < 8; n++) {
            int d = n * 8 + tg * 2;
            Osm[(d)     * 132 + qb]     = Oacc[mt][n][0];
            Osm[(d + 1) * 132 + qb]     = Oacc[mt][n][1];
            Osm[(d)     * 132 + qb + 8] = Oacc[mt][n][2];
            Osm[(d + 1) * 132 + qb + 8] = Oacc[mt][n][3];
        }
    }
    __syncthreads();

    // O: REDG-accumulate across splits (coalesced rows from Osm staging)
    float* ob = g_att + (size_t)bh * CC * CL + l0;
    for (int c = tid; c < 2048; c += 128) {
        int d = c >> 5, q4 = (c & 31) << 2;
        float4 v = *(const float4*)&Osm[d * 132 + q4];
        float* p = &ob[(size_t)d * CL + q4];
        redadd(p + 0, v.x); redadd(p + 1, v.y);
        redadd(p + 2, v.z); redadd(p + 3, v.w);
    }
}

// ============================================================================
// Unify heads on tf32 HMMA; reads the summed O once, scale+rna, GEMM.
// l-tile 32, grid 256 CTAs, occ 2. Slot: O [64 o][36 l] @0, W @9216 (17408B).
// ============================================================================
#define UB_STR  26624
#define U_SMEM  (3 * UB_STR)

__global__ void __launch_bounds__(256, 2) unify_kernel(
    const float* __restrict__ ub, float* __restrict__ y)
{
    extern __shared__ float usm[];
    uint32_t sbU = smem_u32(usm);

    int tid = threadIdx.x;
    int w = tid >> 5, ln = tid & 31, gp = ln >> 2, tg = ln & 3;
    int wm = w & 3, wn = w >> 2;
    int l0 = blockIdx.x * 32, b = blockIdx.y;

    auto issue = [&](int t) {
        uint32_t base = sbU + (t % 3) * UB_STR;
        const float* ag = g_att + (size_t)(b * CO + t * 64) * CL + l0;
        for (int i = tid; i < 512; i += 256) {
            int o = i >> 3, j = i & 7;
            cpa16(base + o * 144 + j * 16, ag + (size_t)o * CL + j * 4);
        }
        const float* wg = g_uwt + t * 64;
        for (int i = tid; i < 1024; i += 256) {
            int c = i >> 4, j = i & 15;
            cpa16(base + 9216 + c * 272 + j * 16, wg + (size_t)c * CO + j * 4);
        }
        CP_COMMIT();
    };

    issue(0);
    issue(1);

    float acc[2][4];
    #pragma unroll
    for (int ns = 0; ns < 2; ns++)
        #pragma unroll
        for (int r = 0; r < 4; r++) acc[ns][r] = 0.f;

    for (int t = 0; t < 8; t++) {
        if (t < 7) { CP_WAIT(1); } else { CP_WAIT(0); }
        __syncthreads();
        if (t + 2 < 8) issue(t + 2);

        float* O0 = usm + (t % 3) * (UB_STR / 4);   // [o][36 l]
        const float* Aw = O0 + 2304;                // [c][68 o]

        // att = O * (1/rs), rna; in place
        {
            int lcol = tid & 31, og = tid >> 5;
            float inv = 1.0f / g_rs[(size_t)(b * CH + t) * CL + l0 + lcol];
            #pragma unroll
            for (int k = 0; k < 8; k++) {
                int o = og * 8 + k;
                O0[o * 36 + lcol] = tf32rna(O0[o * 36 + lcol] * inv);
            }
        }
        __syncthreads();

        #pragma unroll
        for (int ks = 0; ks < 8; ks++) {
            int k0 = ks * 8;
            int ra = (wm * 16 + gp) * 68 + k0;
            uint32_t a0 = *(const uint32_t*)&Aw[ra + tg];
            uint32_t a1 = *(const uint32_t*)&Aw[ra + 8 * 68 + tg];
            uint32_t a2 = *(const uint32_t*)&Aw[ra + tg + 4];
            uint32_t a3 = *(const uint32_t*)&Aw[ra + 8 * 68 + tg + 4];
            int rb0 = (k0 + tg) * 36 + wn * 16 + gp;
            int rb1 = (k0 + tg + 4) * 36 + wn * 16 + gp;
            #pragma unroll
            for (int ns = 0; ns < 2; ns++) {
                uint32_t b0 = *(const uint32_t*)&O0[rb0 + ns * 8];
                uint32_t b1 = *(const uint32_t*)&O0[rb1 + ns * 8];
                tmma(acc[ns], a0, a1, a2, a3, b0, b1);
            }
        }
    }

    __syncthreads();
    float* stg = usm;   // [64 c][36 l]
    #pragma unroll
    for (int ns = 0; ns < 2; ns++) {
        int lcol = wn * 16 + ns * 8 + tg * 2;
        int c = wm * 16 + gp;
        *(float2*)&stg[(c)     * 36 + lcol] = make_float2(acc[ns][0], acc[ns][1]);
        *(float2*)&stg[(c + 8) * 36 + lcol] = make_float2(acc[ns][2], acc[ns][3]);
    }
    __syncthreads();

    for (int i = tid; i < 512; i += 256) {
        int c = i >> 3, l4 = (i & 7) << 2;
        float bb = ub[c];
        float4 v = *(const float4*)&stg[c * 36 + l4];
        v.x += bb; v.y += bb; v.z += bb; v.w += bb;
        *(float4*)&y[(size_t)(b * CC + c) * CL + l0 + l4] = v;
    }
}

// ============================================================================
extern "C" void kernel_launch(void* const* d_in, const int* in_sizes, int n_in,
                              void* d_out, int out_size)
{
    (void)in_sizes; (void)n_in; (void)out_size;
    const float* x    = (const float*)d_in[0];
    const float* q_dw = (const float*)d_in[1];
    const float* q_db = (const float*)d_in[2];
    const float* q_pw = (const float*)d_in[3];
    const float* q_pb = (const float*)d_in[4];
    const float* k_dw = (const float*)d_in[5];
    const float* k_db = (const float*)d_in[6];
    const float* k_pw = (const float*)d_in[7];
    const float* k_pb = (const float*)d_in[8];
    const float* v_dw = (const float*)d_in[9];
    const float* v_db = (const float*)d_in[10];
    const float* v_pw = (const float*)d_in[11];
    const float* v_pb = (const float*)d_in[12];
    const float* u_w  = (const float*)d_in[13];
    const float* u_b  = (const float*)d_in[14];

    cudaFuncSetAttribute(qkv_kernel,
                         cudaFuncAttributeMaxDynamicSharedMemorySize, QKV_SMEM);
    cudaFuncSetAttribute(flash_kernel,
                         cudaFuncAttributeMaxDynamicSharedMemorySize, FL_SMEM);
    cudaFuncSetAttribute(unify_kernel,
                         cudaFuncAttributeMaxDynamicSharedMemorySize, U_SMEM);

    zero_kernel<<<NZ_GRID, 256>>>();
    prep_kernel<<<128, 256>>>(q_pw, k_pw, v_pw, u_w);

    qkv_kernel<<<dim3(CL / 64, CB, 3), 512, QKV_SMEM>>>(
        x, q_dw, q_db, q_pb, k_dw, k_db, k_pb, v_dw, v_db, v_pb);

    flash_kernel<<<dim3(CL / 128, CH, CB * 2), 128, FL_SMEM>>>();

    unify_kernel<<<dim3(CL / 32, CB), 256, U_SMEM>>>(u_b, (float*)d_out);
}

// round 13
// speedup vs baseline: 1.0615x; 1.0316x over previous
#include <cuda_runtime.h>
#include <cuda_bf16.h>
#include <cstdint>

#define CB 4
#define CC 64
#define CH 8
#define CL 2048
#define CO 512

#define QK_SCALE 0.35355339059327373f
#define LOG2E    1.4426950408889634f

// ---------------- bf16x2 exp2 path ----------------
__device__ __forceinline__ uint32_t cvt2bf(float hi, float lo) {
    uint32_t d; asm("cvt.rn.bf16x2.f32 %0, %1, %2;" : "=r"(d) : "f"(hi), "f"(lo)); return d;
}
__device__ __forceinline__ uint32_t ex2bf2(uint32_t x) {
    uint32_t d; asm("ex2.approx.ftz.bf16x2 %0, %1;" : "=r"(d) : "r"(x)); return d;
}
#define ONESBF 0x3F803F80u

__device__ __forceinline__ float tf32rna(float x) {
    uint32_t d; asm("cvt.rna.tf32.f32 %0, %1;" : "=r"(d) : "f"(x));
    return __uint_as_float(d);
}

// ---------------- cp.async ----------------
__device__ __forceinline__ void cpa16(uint32_t s, const void* g) {
    asm volatile("cp.async.cg.shared.global [%0], [%1], 16;" :: "r"(s), "l"(g));
}
#define CP_COMMIT() asm volatile("cp.async.commit_group;" ::: "memory")
#define CP_WAIT(n)  asm volatile("cp.async.wait_group %0;" :: "n"(n) : "memory")

__device__ __forceinline__ uint32_t smem_u32(const void* p) {
    uint32_t a;
    asm("{ .reg .u64 t; cvta.to.shared.u64 t, %1; cvt.u32.u64 %0, t; }" : "=r"(a) : "l"(p));
    return a;
}

// ---------------- HMMA m16n8k16 bf16 ----------------
__device__ __forceinline__ void hmma(float* c,
                                     uint32_t a0, uint32_t a1, uint32_t a2, uint32_t a3,
                                     uint32_t b0, uint32_t b1) {
    asm volatile(
        "mma.sync.aligned.m16n8k16.row.col.f32.bf16.bf16.f32 "
        "{%0,%1,%2,%3},{%4,%5,%6,%7},{%8,%9},{%0,%1,%2,%3};"
        : "+f"(c[0]), "+f"(c[1]), "+f"(c[2]), "+f"(c[3])
        : "r"(a0), "r"(a1), "r"(a2), "r"(a3), "r"(b0), "r"(b1));
}
__device__ __forceinline__ void hmma_z(float* d,
                                       uint32_t a0, uint32_t a1, uint32_t a2, uint32_t a3,
                                       uint32_t b0, uint32_t b1) {
    asm volatile(
        "mma.sync.aligned.m16n8k16.row.col.f32.bf16.bf16.f32 "
        "{%0,%1,%2,%3},{%4,%5,%6,%7},{%8,%9},{%10,%11,%12,%13};"
        : "=f"(d[0]), "=f"(d[1]), "=f"(d[2]), "=f"(d[3])
        : "r"(a0), "r"(a1), "r"(a2), "r"(a3), "r"(b0), "r"(b1),
          "f"(0.f), "f"(0.f), "f"(0.f), "f"(0.f));
}

// ---------------- HMMA m16n8k8 tf32 ----------------
__device__ __forceinline__ void tmma(float* c,
                                     uint32_t a0, uint32_t a1, uint32_t a2, uint32_t a3,
                                     uint32_t b0, uint32_t b1) {
    asm volatile(
        "mma.sync.aligned.m16n8k8.row.col.f32.tf32.tf32.f32 "
        "{%0,%1,%2,%3},{%4,%5,%6,%7},{%8,%9},{%0,%1,%2,%3};"
        : "+f"(c[0]), "+f"(c[1]), "+f"(c[2]), "+f"(c[3])
        : "r"(a0), "r"(a1), "r"(a2), "r"(a3), "r"(b0), "r"(b1));
}

__device__ __forceinline__ void ldsm4(uint32_t a, uint32_t& r0, uint32_t& r1,
                                      uint32_t& r2, uint32_t& r3) {
    asm volatile("ldmatrix.sync.aligned.m8n8.x4.shared.b16 {%0,%1,%2,%3}, [%4];"
        : "=r"(r0), "=r"(r1), "=r"(r2), "=r"(r3) : "r"(a));
}

// ---------------- scratch ----------------
__device__ __nv_bfloat16 g_qt[CB * CH * CL * CC];   // [bh][l][c]  (q prescaled)
__device__ __nv_bfloat16 g_kt[CB * CH * CL * CC];   // [bh][l][c]
__device__ __nv_bfloat16 g_vv[CB * CH * CC * CL];   // [bh][d][l]
__device__ float g_att[2 * CB * CO * CL];           // raw partial O per split; slot 0 overwritten by combine
__device__ float g_rs[2 * CB * CH * CL];            // partial rowsums per split
__device__ __nv_bfloat16 g_w[3 * CO * CC];          // preconverted pw (scales folded)
__device__ float g_uwt[CC * CO];                    // u_w rounded to tf32 (rna)

// ============================================================================
// Prep
// ============================================================================
__global__ __launch_bounds__(256) void prep_kernel(
    const float* __restrict__ qpw, const float* __restrict__ kpw,
    const float* __restrict__ vpw, const float* __restrict__ uw)
{
    int i = blockIdx.x * 256 + threadIdx.x;
    if (i < 24576) {
        int var = i / 8192;
        int off = (i - var * 8192) * 4;
        const float* src = (var == 0) ? qpw : (var == 1) ? kpw : vpw;
        float s = (var == 0) ? QK_SCALE * LOG2E : (var == 1) ? QK_SCALE : 1.0f;
        float4 wv = *(const float4*)&src[off];
        __nv_bfloat162 h0 = __floats2bfloat162_rn(wv.x * s, wv.y * s);
        __nv_bfloat162 h1 = __floats2bfloat162_rn(wv.z * s, wv.w * s);
        *(uint2*)&g_w[var * (CO * CC) + off] = make_uint2(*(uint32_t*)&h0, *(uint32_t*)&h1);
    } else {
        int off = (i - 24576) * 4;
        float4 wv = *(const float4*)&uw[off];
        wv.x = tf32rna(wv.x); wv.y = tf32rna(wv.y);
        wv.z = tf32rna(wv.z); wv.w = tf32rna(wv.w);
        *(float4*)&g_uwt[off] = wv;
    }
}

// ============================================================================
// QKV on HMMA. CTA = (64-seq tile, b, var*2 + headhalf): 4 heads per CTA,
// 256 threads (8 warps; warps 2j,2j+1 own head hh*4+j), occupancy 2.
// smem: ysb [64 l][72 c] @0 (9216B); wsb [256 o][72 c] @9216 (36864B).
// ============================================================================
#define QKV_SMEM 46080

__global__ void __launch_bounds__(256, 2) qkv_kernel(
    const float* __restrict__ x,
    const float* __restrict__ qdw, const float* __restrict__ qdb,
    const float* __restrict__ qpb,
    const float* __restrict__ kdw, const float* __restrict__ kdb,
    const float* __restrict__ kpb,
    const float* __restrict__ vdw, const float* __restrict__ vdb,
    const float* __restrict__ vpb)
{
    extern __shared__ char qsm[];
    __nv_bfloat16* ysb = (__nv_bfloat16*)qsm;            // [64 l][72 c]
    __nv_bfloat16* wsb = (__nv_bfloat16*)(qsm + 9216);   // [256 o][72 c]
    uint32_t sb = smem_u32(qsm);

    int var = blockIdx.z >> 1;
    int hh  = blockIdx.z & 1;    // head half: heads [hh*4, hh*4+4)
    const float* dw = (var == 0) ? qdw : (var == 1) ? kdw : vdw;
    const float* db = (var == 0) ? qdb : (var == 1) ? kdb : vdb;
    const float* pb = (var == 0) ? qpb : (var == 1) ? kpb : vpb;
    float bscale   = (var == 0) ? QK_SCALE * LOG2E : (var == 1) ? QK_SCALE : 1.0f;

    int l0 = blockIdx.x * 64;
    int b  = blockIdx.y;
    int tid = threadIdx.x;
    int w = tid >> 5, ln = tid & 31, gp = ln >> 2, tg = ln & 3;
    int hj = w >> 1, lh = w & 1;   // head-in-CTA, l-half

    // weights for this head-half (256 o rows)
    const __nv_bfloat16* wg = g_w + (size_t)var * (CO * CC) + (size_t)(hh * 256) * CC;
    for (int i = tid; i < 2048; i += 256) {
        int r = i >> 3, j = i & 7;
        cpa16(sb + 9216 + r * 144 + j * 16, wg + (size_t)r * CC + j * 8);
    }
    CP_COMMIT();

    for (int idx = tid; idx < 64 * 64; idx += 256) {
        int c = idx >> 6, li = idx & 63;
        int l = l0 + li;
        const float* xr = x + (size_t)(b * CC + c) * CL;
        float w0 = dw[c * 3 + 0], w1 = dw[c * 3 + 1], w2 = dw[c * 3 + 2];
        float xm = (l > 0)      ? xr[l - 1] : 0.f;
        float x0 = xr[l];
        float xp = (l < CL - 1) ? xr[l + 1] : 0.f;
        ysb[li * 72 + c] = __float2bfloat16(db[c] + w0 * xm + w1 * x0 + w2 * xp);
    }
    CP_WAIT(0);
    __syncthreads();

    int obase = hj * 64;   // within the 256-row wsb
    float pbv[4][2];
    #pragma unroll
    for (int mt = 0; mt < 4; mt++) {
        pbv[mt][0] = pb[hh * 256 + obase + mt * 16 + gp] * bscale;
        pbv[mt][1] = pb[hh * 256 + obase + mt * 16 + gp + 8] * bscale;
    }

    float acc[4][4][4];
    #pragma unroll
    for (int mt = 0; mt < 4; mt++)
        #pragma unroll
        for (int n = 0; n < 4; n++)
            #pragma unroll
            for (int r = 0; r < 4; r++) acc[mt][n][r] = 0.f;

    #pragma unroll
    for (int ks = 0; ks < 4; ks++) {
        uint32_t af[4][4];
        #pragma unroll
        for (int mt = 0; mt < 4; mt++) {
            int row = obase + mt * 16 + gp;
            int col = ks * 16 + tg * 2;
            af[mt][0] = *(const uint32_t*)&wsb[(row)     * 72 + col];
            af[mt][1] = *(const uint32_t*)&wsb[(row + 8) * 72 + col];
            af[mt][2] = *(const uint32_t*)&wsb[(row)     * 72 + col + 8];
            af[mt][3] = *(const uint32_t*)&wsb[(row + 8) * 72 + col + 8];
        }
        #pragma unroll
        for (int n = 0; n < 4; n++) {
            int nrow = lh * 32 + n * 8 + gp, ncol = ks * 16 + tg * 2;
            uint32_t b0 = *(const uint32_t*)&ysb[nrow * 72 + ncol];
            uint32_t b1 = *(const uint32_t*)&ysb[nrow * 72 + ncol + 8];
            #pragma unroll
            for (int mt = 0; mt < 4; mt++)
                hmma(acc[mt][n], af[mt][0], af[mt][1], af[mt][2], af[mt][3], b0, b1);
        }
    }

    __syncthreads();   // all warps done reading wsb weights

    __nv_bfloat16* stg = wsb + hj * 4608;   // [64][72]
    if (var == 2) {
        #pragma unroll
        for (int mt = 0; mt < 4; mt++)
            #pragma unroll
            for (int n = 0; n < 4; n++) {
                int d = mt * 16 + gp, lcol = lh * 32 + n * 8 + tg * 2;
                __nv_bfloat162 h0 = __floats2bfloat162_rn(acc[mt][n][0] + pbv[mt][0],
                                                          acc[mt][n][1] + pbv[mt][0]);
                __nv_bfloat162 h1 = __floats2bfloat162_rn(acc[mt][n][2] + pbv[mt][1],
                                                          acc[mt][n][3] + pbv[mt][1]);
                *(uint32_t*)&stg[(d)     * 72 + lcol] = *(uint32_t*)&h0;
                *(uint32_t*)&stg[(d + 8) * 72 + lcol] = *(uint32_t*)&h1;
            }
    } else {
        #pragma unroll
        for (int mt = 0; mt < 4; mt++)
            #pragma unroll
            for (int n = 0; n < 4; n++) {
                int d = mt * 16 + gp, lcol = lh * 32 + n * 8 + tg * 2;
                stg[(lcol)     * 72 + d]     = __float2bfloat16(acc[mt][n][0] + pbv[mt][0]);
                stg[(lcol + 1) * 72 + d]     = __float2bfloat16(acc[mt][n][1] + pbv[mt][0]);
                stg[(lcol)     * 72 + d + 8] = __float2bfloat16(acc[mt][n][2] + pbv[mt][1]);
                stg[(lcol + 1) * 72 + d + 8] = __float2bfloat16(acc[mt][n][3] + pbv[mt][1]);
            }
    }
    __syncthreads();

    int bh = b * CH + hh * 4 + hj;
    int lane64 = lh * 32 + ln;
    if (var == 2) {
        for (int i = lane64; i < 512; i += 64) {
            int r = i >> 3, j = i & 7;
            *(uint4*)&g_vv[((size_t)(bh * CC + r)) * CL + l0 + j * 8] =
                *(const uint4*)&stg[r * 72 + j * 8];
        }
    } else {
        __nv_bfloat16* outp = (var == 0) ? g_qt : g_kt;
        for (int i = lane64; i < 512; i += 64) {
            int r = i >> 3, j = i & 7;
            *(uint4*)&outp[((size_t)bh * CL + l0 + r) * CC + j * 8] =
                *(const uint4*)&stg[r * 72 + j * 8];
        }
    }
}

// ============================================================================
// Flash attention, split-K=2, 128 threads, occ 3 (round-10 shape, plain STG).
// ============================================================================
#define KT      64
#define NT      (CL / KT / 2)
#define KV_OFF  18432
#define KV_STR  18432
#define FL_SMEM 55296

__global__ void __launch_bounds__(128, 3) flash_kernel()
{
    extern __shared__ char sm[];
    uint32_t sb = smem_u32(sm);
    float* Osm = (float*)sm;

    int tid = threadIdx.x;
    int w   = tid >> 5;
    int ln  = tid & 31;
    int gp  = ln >> 2;
    int tg  = ln & 3;
    int l0  = blockIdx.x * 128;
    int s   = blockIdx.z & 1;
    int bh  = (blockIdx.z >> 1) * CH + blockIdx.y;
    int kbase0 = s * (CL / 2);

    int t4 = ln >> 3;
    uint32_t lk  = (((t4 >> 1) * 8 + (ln & 7)) * 144) + ((t4 & 1) * 16);
    uint32_t qlk = (((t4 & 1) * 8 + (ln & 7)) * 144) + ((t4 >> 1) * 16);
    uint32_t qwarp = sb + (uint32_t)(w * 32) * 144 + qlk;

    const __nv_bfloat16* qg = g_qt + (size_t)bh * CL * CC;
    const __nv_bfloat16* kg = g_kt + (size_t)bh * CL * CC;
    const __nv_bfloat16* vg = g_vv + (size_t)bh * CC * CL;

    for (int c = tid; c < 1024; c += 128) {
        int r = c >> 3, j = c & 7;
        cpa16(sb + r * 144 + j * 16, qg + ((size_t)(l0 + r)) * CC + j * 8);
    }
    for (int c = tid; c < 512; c += 128) {
        int r = c >> 3, j = c & 7;
        cpa16(sb + KV_OFF + r * 144 + j * 16, kg + ((size_t)(kbase0 + r)) * CC + j * 8);
        cpa16(sb + KV_OFF + 9216 + r * 144 + j * 16, vg + (size_t)r * CL + kbase0 + j * 8);
    }
    CP_COMMIT();
    CP_WAIT(0);
    __syncthreads();

    float Oacc[2][8][4];
    #pragma unroll
    for (int mt = 0; mt < 2; mt++)
        #pragma unroll
        for (int n = 0; n < 8; n++)
            #pragma unroll
            for (int r = 0; r < 4; r++) Oacc[mt][n][r] = 0.f;
    float Racc[2][4];
    #pragma unroll
    for (int mt = 0; mt < 2; mt++)
        #pragma unroll
        for (int r = 0; r < 4; r++) Racc[mt][r] = 0.f;

    for (int i = 0; i < NT; i++) {
        if (i > 0) CP_WAIT(0);
        __syncthreads();

        if (i + 1 < NT) {
            int n0 = kbase0 + (i + 1) * KT;
            uint32_t base = sb + KV_OFF + ((i + 1) & 1) * KV_STR;
            for (int c = tid; c < 512; c += 128) {
                int r = c >> 3, j = c & 7;
                cpa16(base + r * 144 + j * 16, kg + ((size_t)(n0 + r)) * CC + j * 8);
                cpa16(base + 9216 + r * 144 + j * 16, vg + (size_t)r * CL + n0 + j * 8);
            }
            CP_COMMIT();
        }

        uint32_t kb = sb + KV_OFF + (i & 1) * KV_STR + lk;
        uint32_t vb = kb + 9216;

        float Sacc[2][8][4];

        #pragma unroll
        for (int ks = 0; ks < 4; ks++) {
            uint32_t qf[2][4];
            #pragma unroll
            for (int mt = 0; mt < 2; mt++)
                ldsm4(qwarp + (uint32_t)(mt * 16) * 144 + ks * 32,
                      qf[mt][0], qf[mt][1], qf[mt][2], qf[mt][3]);
            #pragma unroll
            for (int ng2 = 0; ng2 < 4; ng2++) {
                uint32_t k0, k1, k2, k3;
                ldsm4(kb + ng2 * 2304 + ks * 32, k0, k1, k2, k3);
                if (ks == 0) {
                    hmma_z(Sacc[0][2 * ng2],     qf[0][0], qf[0][1], qf[0][2], qf[0][3], k0, k1);
                    hmma_z(Sacc[0][2 * ng2 + 1], qf[0][0], qf[0][1], qf[0][2], qf[0][3], k2, k3);
                    hmma_z(Sacc[1][2 * ng2],     qf[1][0], qf[1][1], qf[1][2], qf[1][3], k0, k1);
                    hmma_z(Sacc[1][2 * ng2 + 1], qf[1][0], qf[1][1], qf[1][2], qf[1][3], k2, k3);
                } else {
                    hmma(Sacc[0][2 * ng2],     qf[0][0], qf[0][1], qf[0][2], qf[0][3], k0, k1);
                    hmma(Sacc[0][2 * ng2 + 1], qf[0][0], qf[0][1], qf[0][2], qf[0][3], k2, k3);
                    hmma(Sacc[1][2 * ng2],     qf[1][0], qf[1][1], qf[1][2], qf[1][3], k0, k1);
                    hmma(Sacc[1][2 * ng2 + 1], qf[1][0], qf[1][1], qf[1][2], qf[1][3], k2, k3);
                }
            }
        }

        #pragma unroll
        for (int ks = 0; ks < 4; ks++) {
            uint32_t pa[2][4];
            #pragma unroll
            for (int mt = 0; mt < 2; mt++) {
                pa[mt][0] = ex2bf2(cvt2bf(Sacc[mt][2 * ks][1],     Sacc[mt][2 * ks][0]));
                pa[mt][1] = ex2bf2(cvt2bf(Sacc[mt][2 * ks][3],     Sacc[mt][2 * ks][2]));
                pa[mt][2] = ex2bf2(cvt2bf(Sacc[mt][2 * ks + 1][1], Sacc[mt][2 * ks + 1][0]));
                pa[mt][3] = ex2bf2(cvt2bf(Sacc[mt][2 * ks + 1][3], Sacc[mt][2 * ks + 1][2]));
            }
            #pragma unroll
            for (int ng2 = 0; ng2 < 4; ng2++) {
                uint32_t v0, v1, v2, v3;
                ldsm4(vb + ng2 * 2304 + ks * 32, v0, v1, v2, v3);
                hmma(Oacc[0][2 * ng2],     pa[0][0], pa[0][1], pa[0][2], pa[0][3], v0, v1);
                hmma(Oacc[0][2 * ng2 + 1], pa[0][0], pa[0][1], pa[0][2], pa[0][3], v2, v3);
                hmma(Oacc[1][2 * ng2],     pa[1][0], pa[1][1], pa[1][2], pa[1][3], v0, v1);
                hmma(Oacc[1][2 * ng2 + 1], pa[1][0], pa[1][1], pa[1][2], pa[1][3], v2, v3);
            }
            hmma(Racc[0], pa[0][0], pa[0][1], pa[0][2], pa[0][3], ONESBF, ONESBF);
            hmma(Racc[1], pa[1][0], pa[1][1], pa[1][2], pa[1][3], ONESBF, ONESBF);
        }
    }

    float* rsb = g_rs + (size_t)s * (CB * CH * CL) + (size_t)bh * CL + l0;
    if (tg == 0) {
        #pragma unroll
        for (int mt = 0; mt < 2; mt++) {
            rsb[w * 32 + mt * 16 + gp]     = Racc[mt][0];
            rsb[w * 32 + mt * 16 + gp + 8] = Racc[mt][2];
        }
    }

    __syncthreads();
    #pragma unroll
    for (int mt = 0; mt < 2; mt++) {
        int qb = w * 32 + mt * 16 + gp;
        #pragma unroll
        for (int n = 0; n < 8; n++) {
            int d = n * 8 + tg * 2;
            Osm[(d)     * 132 + qb]     = Oacc[mt][n][0];
            Osm[(d + 1) * 132 + qb]     = Oacc[mt][n][1];
            Osm[(d)     * 132 + qb + 8] = Oacc[mt][n][2];
            Osm[(d + 1) * 132 + qb + 8] = Oacc[mt][n][3];
        }
    }
    __syncthreads();

    float* ob = g_att + (size_t)s * (CB * CO * CL) + (size_t)bh * CC * CL + l0;
    for (int c = tid; c < 2048; c += 128) {
        int d = c >> 5, q4 = (c & 31) << 2;
        *(float4*)&ob[(size_t)d * CL + q4] = *(const float4*)&Osm[d * 132 + q4];
    }
}

// ============================================================================
// Combine: att = rna((O0 + O1) * 1/(rs0 + rs1)), in place into g_att[0].
// Pure streaming float4; rs lines are L2-hot (reused by 64 d's).
// ============================================================================
#define CMB_N (CB * CO * CL / 4)   // 1,048,576 float4

__global__ __launch_bounds__(256) void combine_kernel()
{
    int i = blockIdx.x * 256 + threadIdx.x;
    if (i >= CMB_N) return;
    int lin = i << 2;
    int l   = lin & (CL - 1);
    int bh  = lin >> 17;          // / (CC*CL)

    float4 o0 = *(const float4*)&g_att[lin];
    float4 o1 = *(const float4*)&g_att[CB * CO * CL + lin];
    const float* rsp = g_rs + (size_t)bh * CL + l;
    float4 r0 = *(const float4*)rsp;
    float4 r1 = *(const float4*)(rsp + CB * CH * CL);

    float4 out;
    out.x = tf32rna((o0.x + o1.x) / (r0.x + r1.x));
    out.y = tf32rna((o0.y + o1.y) / (r0.y + r1.y));
    out.z = tf32rna((o0.z + o1.z) / (r0.z + r1.z));
    out.w = tf32rna((o0.w + o1.w) / (r0.w + r1.w));
    *(float4*)&g_att[lin] = out;
}

// ============================================================================
// Unify heads on tf32 HMMA; reads combined att, no per-chunk combine.
// l-tile 32, grid 256 CTAs, occ 2. Slot: O [64 o][36 l] @0, W @9216 (17408B).
// ============================================================================
#define UB_STR  26624
#define U_SMEM  (3 * UB_STR)

__global__ void __launch_bounds__(256, 2) unify_kernel(
    const float* __restrict__ ub, float* __restrict__ y)
{
    extern __shared__ float usm[];
    uint32_t sbU = smem_u32(usm);

    int tid = threadIdx.x;
    int w = tid >> 5, ln = tid & 31, gp = ln >> 2, tg = ln & 3;
    int wm = w & 3, wn = w >> 2;
    int l0 = blockIdx.x * 32, b = blockIdx.y;

    auto issue = [&](int t) {
        uint32_t base = sbU + (t % 3) * UB_STR;
        const float* ag = g_att + (size_t)(b * CO + t * 64) * CL + l0;
        for (int i = tid; i < 512; i += 256) {
            int o = i >> 3, j = i & 7;
            cpa16(base + o * 144 + j * 16, ag + (size_t)o * CL + j * 4);
        }
        const float* wg = g_uwt + t * 64;
        for (int i = tid; i < 1024; i += 256) {
            int c = i >> 4, j = i & 15;
            cpa16(base + 9216 + c * 272 + j * 16, wg + (size_t)c * CO + j * 4);
        }
        CP_COMMIT();
    };

    issue(0);
    issue(1);

    float acc[2][4];
    #pragma unroll
    for (int ns = 0; ns < 2; ns++)
        #pragma unroll
        for (int r = 0; r < 4; r++) acc[ns][r] = 0.f;

    for (int t = 0; t < 8; t++) {
        if (t < 7) { CP_WAIT(1); } else { CP_WAIT(0); }
        __syncthreads();
        if (t + 2 < 8) issue(t + 2);

        const float* O0 = usm + (t % 3) * (UB_STR / 4);   // [o][36 l] (combined att)
        const float* Aw = O0 + 2304;                      // [c][68 o]

        #pragma unroll
        for (int ks = 0; ks < 8; ks++) {
            int k0 = ks * 8;
            int ra = (wm * 16 + gp) * 68 + k0;
            uint32_t a0 = *(const uint32_t*)&Aw[ra + tg];
            uint32_t a1 = *(const uint32_t*)&Aw[ra + 8 * 68 + tg];
            uint32_t a2 = *(const uint32_t*)&Aw[ra + tg + 4];
            uint32_t a3 = *(const uint32_t*)&Aw[ra + 8 * 68 + tg + 4];
            int rb0 = (k0 + tg) * 36 + wn * 16 + gp;
            int rb1 = (k0 + tg + 4) * 36 + wn * 16 + gp;
            #pragma unroll
            for (int ns = 0; ns < 2; ns++) {
                uint32_t b0 = *(const uint32_t*)&O0[rb0 + ns * 8];
                uint32_t b1 = *(const uint32_t*)&O0[rb1 + ns * 8];
                tmma(acc[ns], a0, a1, a2, a3, b0, b1);
            }
        }
    }

    __syncthreads();
    float* stg = usm;   // [64 c][36 l]
    #pragma unroll
    for (int ns = 0; ns < 2; ns++) {
        int lcol = wn * 16 + ns * 8 + tg * 2;
        int c = wm * 16 + gp;
        *(float2*)&stg[(c)     * 36 + lcol] = make_float2(acc[ns][0], acc[ns][1]);
        *(float2*)&stg[(c + 8) * 36 + lcol] = make_float2(acc[ns][2], acc[ns][3]);
    }
    __syncthreads();

    for (int i = tid; i < 512; i += 256) {
        int c = i >> 3, l4 = (i & 7) << 2;
        float bb = ub[c];
        float4 v = *(const float4*)&stg[c * 36 + l4];
        v.x += bb; v.y += bb; v.z += bb; v.w += bb;
        *(float4*)&y[(size_t)(b * CC + c) * CL + l0 + l4] = v;
    }
}

// ============================================================================
extern "C" void kernel_launch(void* const* d_in, const int* in_sizes, int n_in,
                              void* d_out, int out_size)
{
    (void)in_sizes; (void)n_in; (void)out_size;
    const float* x    = (const float*)d_in[0];
    const float* q_dw = (const float*)d_in[1];
    const float* q_db = (const float*)d_in[2];
    const float* q_pw = (const float*)d_in[3];
    const float* q_pb = (const float*)d_in[4];
    const float* k_dw = (const float*)d_in[5];
    const float* k_db = (const float*)d_in[6];
    const float* k_pw = (const float*)d_in[7];
    const float* k_pb = (const float*)d_in[8];
    const float* v_dw = (const float*)d_in[9];
    const float* v_db = (const float*)d_in[10];
    const float* v_pw = (const float*)d_in[11];
    const float* v_pb = (const float*)d_in[12];
    const float* u_w  = (const float*)d_in[13];
    const float* u_b  = (const float*)d_in[14];

    cudaFuncSetAttribute(qkv_kernel,
                         cudaFuncAttributeMaxDynamicSharedMemorySize, QKV_SMEM);
    cudaFuncSetAttribute(flash_kernel,
                         cudaFuncAttributeMaxDynamicSharedMemorySize, FL_SMEM);
    cudaFuncSetAttribute(unify_kernel,
                         cudaFuncAttributeMaxDynamicSharedMemorySize, U_SMEM);

    prep_kernel<<<128, 256>>>(q_pw, k_pw, v_pw, u_w);

    qkv_kernel<<<dim3(CL / 64, CB, 6), 256, QKV_SMEM>>>(
        x, q_dw, q_db, q_pb, k_dw, k_db, k_pb, v_dw, v_db, v_pb);

    flash_kernel<<<dim3(CL / 128, CH, CB * 2), 128, FL_SMEM>>>();

    combine_kernel<<<CMB_N / 256, 256>>>();

    unify_kernel<<<dim3(CL / 32, CB), 256, U_SMEM>>>(u_b, (float*)d_out);
}

// round 15
// speedup vs baseline: 1.0821x; 1.0194x over previous
#include <cuda_runtime.h>
#include <cuda_bf16.h>
#include <cstdint>

#define CB 4
#define CC 64
#define CH 8
#define CL 2048
#define CO 512

#define QK_SCALE 0.35355339059327373f
#define LOG2E    1.4426950408889634f

// ---------------- bf16x2 exp2 path ----------------
__device__ __forceinline__ uint32_t cvt2bf(float hi, float lo) {
    uint32_t d; asm("cvt.rn.bf16x2.f32 %0, %1, %2;" : "=r"(d) : "f"(hi), "f"(lo)); return d;
}
__device__ __forceinline__ uint32_t ex2bf2(uint32_t x) {
    uint32_t d; asm("ex2.approx.ftz.bf16x2 %0, %1;" : "=r"(d) : "r"(x)); return d;
}
#define ONESBF 0x3F803F80u

__device__ __forceinline__ float tf32rna(float x) {
    uint32_t d; asm("cvt.rna.tf32.f32 %0, %1;" : "=r"(d) : "f"(x));
    return __uint_as_float(d);
}

// ---------------- cp.async ----------------
__device__ __forceinline__ void cpa16(uint32_t s, const void* g) {
    asm volatile("cp.async.cg.shared.global [%0], [%1], 16;" :: "r"(s), "l"(g));
}
#define CP_COMMIT() asm volatile("cp.async.commit_group;" ::: "memory")
#define CP_WAIT(n)  asm volatile("cp.async.wait_group %0;" :: "n"(n) : "memory")

__device__ __forceinline__ uint32_t smem_u32(const void* p) {
    uint32_t a;
    asm("{ .reg .u64 t; cvta.to.shared.u64 t, %1; cvt.u32.u64 %0, t; }" : "=r"(a) : "l"(p));
    return a;
}

// ---------------- HMMA m16n8k16 bf16 ----------------
__device__ __forceinline__ void hmma(float* c,
                                     uint32_t a0, uint32_t a1, uint32_t a2, uint32_t a3,
                                     uint32_t b0, uint32_t b1) {
    asm volatile(
        "mma.sync.aligned.m16n8k16.row.col.f32.bf16.bf16.f32 "
        "{%0,%1,%2,%3},{%4,%5,%6,%7},{%8,%9},{%0,%1,%2,%3};"
        : "+f"(c[0]), "+f"(c[1]), "+f"(c[2]), "+f"(c[3])
        : "r"(a0), "r"(a1), "r"(a2), "r"(a3), "r"(b0), "r"(b1));
}
__device__ __forceinline__ void hmma_z(float* d,
                                       uint32_t a0, uint32_t a1, uint32_t a2, uint32_t a3,
                                       uint32_t b0, uint32_t b1) {
    asm volatile(
        "mma.sync.aligned.m16n8k16.row.col.f32.bf16.bf16.f32 "
        "{%0,%1,%2,%3},{%4,%5,%6,%7},{%8,%9},{%10,%11,%12,%13};"
        : "=f"(d[0]), "=f"(d[1]), "=f"(d[2]), "=f"(d[3])
        : "r"(a0), "r"(a1), "r"(a2), "r"(a3), "r"(b0), "r"(b1),
          "f"(0.f), "f"(0.f), "f"(0.f), "f"(0.f));
}

// ---------------- HMMA m16n8k8 tf32 ----------------
__device__ __forceinline__ void tmma(float* c,
                                     uint32_t a0, uint32_t a1, uint32_t a2, uint32_t a3,
                                     uint32_t b0, uint32_t b1) {
    asm volatile(
        "mma.sync.aligned.m16n8k8.row.col.f32.tf32.tf32.f32 "
        "{%0,%1,%2,%3},{%4,%5,%6,%7},{%8,%9},{%0,%1,%2,%3};"
        : "+f"(c[0]), "+f"(c[1]), "+f"(c[2]), "+f"(c[3])
        : "r"(a0), "r"(a1), "r"(a2), "r"(a3), "r"(b0), "r"(b1));
}

__device__ __forceinline__ void ldsm4(uint32_t a, uint32_t& r0, uint32_t& r1,
                                      uint32_t& r2, uint32_t& r3) {
    asm volatile("ldmatrix.sync.aligned.m8n8.x4.shared.b16 {%0,%1,%2,%3}, [%4];"
        : "=r"(r0), "=r"(r1), "=r"(r2), "=r"(r3) : "r"(a));
}

// ---------------- scratch ----------------
__device__ __nv_bfloat16 g_qt[CB * CH * CL * CC];   // [bh][l][c]  (q prescaled)
__device__ __nv_bfloat16 g_kt[CB * CH * CL * CC];   // [bh][l][c]
__device__ __nv_bfloat16 g_vv[CB * CH * CC * CL];   // [bh][d][l]
__device__ float g_att[2 * CB * CO * CL];           // raw partial O per split; slot 0 gets combined att
__device__ float g_rs[2 * CB * CH * CL];            // partial rowsums per split
__device__ __nv_bfloat16 g_w[3 * CO * CC];          // preconverted pw (scales folded)
__device__ float g_uwt[CC * CO];                    // u_w rounded to tf32 (rna)

// ============================================================================
// Prep
// ============================================================================
__global__ __launch_bounds__(256) void prep_kernel(
    const float* __restrict__ qpw, const float* __restrict__ kpw,
    const float* __restrict__ vpw, const float* __restrict__ uw)
{
    int i = blockIdx.x * 256 + threadIdx.x;
    if (i < 24576) {
        int var = i / 8192;
        int off = (i - var * 8192) * 4;
        const float* src = (var == 0) ? qpw : (var == 1) ? kpw : vpw;
        float s = (var == 0) ? QK_SCALE * LOG2E : (var == 1) ? QK_SCALE : 1.0f;
        float4 wv = *(const float4*)&src[off];
        __nv_bfloat162 h0 = __floats2bfloat162_rn(wv.x * s, wv.y * s);
        __nv_bfloat162 h1 = __floats2bfloat162_rn(wv.z * s, wv.w * s);
        *(uint2*)&g_w[var * (CO * CC) + off] = make_uint2(*(uint32_t*)&h0, *(uint32_t*)&h1);
    } else {
        int off = (i - 24576) * 4;
        float4 wv = *(const float4*)&uw[off];
        wv.x = tf32rna(wv.x); wv.y = tf32rna(wv.y);
        wv.z = tf32rna(wv.z); wv.w = tf32rna(wv.w);
        *(float4*)&g_uwt[off] = wv;
    }
}

// ============================================================================
// QKV on HMMA (round-9 shape: 512 threads, 16 warps, all 8 heads per CTA).
// ============================================================================
#define QKV_SMEM 82944

__global__ void __launch_bounds__(512) qkv_kernel(
    const float* __restrict__ x,
    const float* __restrict__ qdw, const float* __restrict__ qdb,
    const float* __restrict__ qpb,
    const float* __restrict__ kdw, const float* __restrict__ kdb,
    const float* __restrict__ kpb,
    const float* __restrict__ vdw, const float* __restrict__ vdb,
    const float* __restrict__ vpb)
{
    extern __shared__ char qsm[];
    __nv_bfloat16* ysb = (__nv_bfloat16*)qsm;            // [64 l][72 c]
    __nv_bfloat16* wsb = (__nv_bfloat16*)(qsm + 9216);   // [512 o][72 c]
    uint32_t sb = smem_u32(qsm);

    int var = blockIdx.z;
    const float* dw = (var == 0) ? qdw : (var == 1) ? kdw : vdw;
    const float* db = (var == 0) ? qdb : (var == 1) ? kdb : vdb;
    const float* pb = (var == 0) ? qpb : (var == 1) ? kpb : vpb;
    float bscale   = (var == 0) ? QK_SCALE * LOG2E : (var == 1) ? QK_SCALE : 1.0f;

    int l0 = blockIdx.x * 64;
    int b  = blockIdx.y;
    int tid = threadIdx.x;
    int w = tid >> 5, ln = tid & 31, gp = ln >> 2, tg = ln & 3;
    int head = w >> 1, lh = w & 1;

    const __nv_bfloat16* wg = g_w + (size_t)var * (CO * CC);
    for (int i = tid; i < 4096; i += 512) {
        int r = i >> 3, j = i & 7;
        cpa16(sb + 9216 + r * 144 + j * 16, wg + (size_t)r * CC + j * 8);
    }
    CP_COMMIT();

    for (int idx = tid; idx < 64 * 64; idx += 512) {
        int c = idx >> 6, li = idx & 63;
        int l = l0 + li;
        const float* xr = x + (size_t)(b * CC + c) * CL;
        float w0 = dw[c * 3 + 0], w1 = dw[c * 3 + 1], w2 = dw[c * 3 + 2];
        float xm = (l > 0)      ? xr[l - 1] : 0.f;
        float x0 = xr[l];
        float xp = (l < CL - 1) ? xr[l + 1] : 0.f;
        ysb[li * 72 + c] = __float2bfloat16(db[c] + w0 * xm + w1 * x0 + w2 * xp);
    }
    CP_WAIT(0);
    __syncthreads();

    int obase = head * 64;
    float pbv[4][2];
    #pragma unroll
    for (int mt = 0; mt < 4; mt++) {
        pbv[mt][0] = pb[obase + mt * 16 + gp] * bscale;
        pbv[mt][1] = pb[obase + mt * 16 + gp + 8] * bscale;
    }

    float acc[4][4][4];
    #pragma unroll
    for (int mt = 0; mt < 4; mt++)
        #pragma unroll
        for (int n = 0; n < 4; n++)
            #pragma unroll
            for (int r = 0; r < 4; r++) acc[mt][n][r] = 0.f;

    #pragma unroll
    for (int ks = 0; ks < 4; ks++) {
        uint32_t af[4][4];
        #pragma unroll
        for (int mt = 0; mt < 4; mt++) {
            int row = obase + mt * 16 + gp;
            int col = ks * 16 + tg * 2;
            af[mt][0] = *(const uint32_t*)&wsb[(row)     * 72 + col];
            af[mt][1] = *(const uint32_t*)&wsb[(row + 8) * 72 + col];
            af[mt][2] = *(const uint32_t*)&wsb[(row)     * 72 + col + 8];
            af[mt][3] = *(const uint32_t*)&wsb[(row + 8) * 72 + col + 8];
        }
        #pragma unroll
        for (int n = 0; n < 4; n++) {
            int nrow = lh * 32 + n * 8 + gp, ncol = ks * 16 + tg * 2;
            uint32_t b0 = *(const uint32_t*)&ysb[nrow * 72 + ncol];
            uint32_t b1 = *(const uint32_t*)&ysb[nrow * 72 + ncol + 8];
            #pragma unroll
            for (int mt = 0; mt < 4; mt++)
                hmma(acc[mt][n], af[mt][0], af[mt][1], af[mt][2], af[mt][3], b0, b1);
        }
    }

    __syncthreads();

    __nv_bfloat16* stg = wsb + head * 4608;   // [64][72]
    if (var == 2) {
        #pragma unroll
        for (int mt = 0; mt < 4; mt++)
            #pragma unroll
            for (int n = 0; n < 4; n++) {
                int d = mt * 16 + gp, lcol = lh * 32 + n * 8 + tg * 2;
                __nv_bfloat162 h0 = __floats2bfloat162_rn(acc[mt][n][0] + pbv[mt][0],
                                                          acc[mt][n][1] + pbv[mt][0]);
                __nv_bfloat162 h1 = __floats2bfloat162_rn(acc[mt][n][2] + pbv[mt][1],
                                                          acc[mt][n][3] + pbv[mt][1]);
                *(uint32_t*)&stg[(d)     * 72 + lcol] = *(uint32_t*)&h0;
                *(uint32_t*)&stg[(d + 8) * 72 + lcol] = *(uint32_t*)&h1;
            }
    } else {
        #pragma unroll
        for (int mt = 0; mt < 4; mt++)
            #pragma unroll
            for (int n = 0; n < 4; n++) {
                int d = mt * 16 + gp, lcol = lh * 32 + n * 8 + tg * 2;
                stg[(lcol)     * 72 + d]     = __float2bfloat16(acc[mt][n][0] + pbv[mt][0]);
                stg[(lcol + 1) * 72 + d]     = __float2bfloat16(acc[mt][n][1] + pbv[mt][0]);
                stg[(lcol)     * 72 + d + 8] = __float2bfloat16(acc[mt][n][2] + pbv[mt][1]);
                stg[(lcol + 1) * 72 + d + 8] = __float2bfloat16(acc[mt][n][3] + pbv[mt][1]);
            }
    }
    __syncthreads();

    int bh = b * CH + head;
    int lane64 = lh * 32 + ln;
    if (var == 2) {
        for (int i = lane64; i < 512; i += 64) {
            int r = i >> 3, j = i & 7;
            *(uint4*)&g_vv[((size_t)(bh * CC + r)) * CL + l0 + j * 8] =
                *(const uint4*)&stg[r * 72 + j * 8];
        }
    } else {
        __nv_bfloat16* outp = (var == 0) ? g_qt : g_kt;
        for (int i = lane64; i < 512; i += 64) {
            int r = i >> 3, j = i & 7;
            *(uint4*)&outp[((size_t)bh * CL + l0 + r) * CC + j * 8] =
                *(const uint4*)&stg[r * 72 + j * 8];
        }
    }
}

// ============================================================================
// Flash attention, split-K=2, 128 threads, occ 3 (round-10 shape).
// ============================================================================
#define KT      64
#define NT      (CL / KT / 2)
#define KV_OFF  18432
#define KV_STR  18432
#define FL_SMEM 55296

__global__ void __launch_bounds__(128, 3) flash_kernel()
{
    extern __shared__ char sm[];
    uint32_t sb = smem_u32(sm);
    float* Osm = (float*)sm;

    int tid = threadIdx.x;
    int w   = tid >> 5;
    int ln  = tid & 31;
    int gp  = ln >> 2;
    int tg  = ln & 3;
    int l0  = blockIdx.x * 128;
    int s   = blockIdx.z & 1;
    int bh  = (blockIdx.z >> 1) * CH + blockIdx.y;
    int kbase0 = s * (CL / 2);

    int t4 = ln >> 3;
    uint32_t lk  = (((t4 >> 1) * 8 + (ln & 7)) * 144) + ((t4 & 1) * 16);
    uint32_t qlk = (((t4 & 1) * 8 + (ln & 7)) * 144) + ((t4 >> 1) * 16);
    uint32_t qwarp = sb + (uint32_t)(w * 32) * 144 + qlk;

    const __nv_bfloat16* qg = g_qt + (size_t)bh * CL * CC;
    const __nv_bfloat16* kg = g_kt + (size_t)bh * CL * CC;
    const __nv_bfloat16* vg = g_vv + (size_t)bh * CC * CL;

    for (int c = tid; c < 1024; c += 128) {
        int r = c >> 3, j = c & 7;
        cpa16(sb + r * 144 + j * 16, qg + ((size_t)(l0 + r)) * CC + j * 8);
    }
    for (int c = tid; c < 512; c += 128) {
        int r = c >> 3, j = c & 7;
        cpa16(sb + KV_OFF + r * 144 + j * 16, kg + ((size_t)(kbase0 + r)) * CC + j * 8);
        cpa16(sb + KV_OFF + 9216 + r * 144 + j * 16, vg + (size_t)r * CL + kbase0 + j * 8);
    }
    CP_COMMIT();
    CP_WAIT(0);
    __syncthreads();

    float Oacc[2][8][4];
    #pragma unroll
    for (int mt = 0; mt < 2; mt++)
        #pragma unroll
        for (int n = 0; n < 8; n++)
            #pragma unroll
            for (int r = 0; r < 4; r++) Oacc[mt][n][r] = 0.f;
    float Racc[2][4];
    #pragma unroll
    for (int mt = 0; mt < 2; mt++)
        #pragma unroll
        for (int r = 0; r < 4; r++) Racc[mt][r] = 0.f;

    for (int i = 0; i < NT; i++) {
        if (i > 0) CP_WAIT(0);
        __syncthreads();

        if (i + 1 < NT) {
            int n0 = kbase0 + (i + 1) * KT;
            uint32_t base = sb + KV_OFF + ((i + 1) & 1) * KV_STR;
            for (int c = tid; c < 512; c += 128) {
                int r = c >> 3, j = c & 7;
                cpa16(base + r * 144 + j * 16, kg + ((size_t)(n0 + r)) * CC + j * 8);
                cpa16(base + 9216 + r * 144 + j * 16, vg + (size_t)r * CL + n0 + j * 8);
            }
            CP_COMMIT();
        }

        uint32_t kb = sb + KV_OFF + (i & 1) * KV_STR + lk;
        uint32_t vb = kb + 9216;

        float Sacc[2][8][4];

        #pragma unroll
        for (int ks = 0; ks < 4; ks++) {
            uint32_t qf[2][4];
            #pragma unroll
            for (int mt = 0; mt < 2; mt++)
                ldsm4(qwarp + (uint32_t)(mt * 16) * 144 + ks * 32,
                      qf[mt][0], qf[mt][1], qf[mt][2], qf[mt][3]);
            #pragma unroll
            for (int ng2 = 0; ng2 < 4; ng2++) {
                uint32_t k0, k1, k2, k3;
                ldsm4(kb + ng2 * 2304 + ks * 32, k0, k1, k2, k3);
                if (ks == 0) {
                    hmma_z(Sacc[0][2 * ng2],     qf[0][0], qf[0][1], qf[0][2], qf[0][3], k0, k1);
                    hmma_z(Sacc[0][2 * ng2 + 1], qf[0][0], qf[0][1], qf[0][2], qf[0][3], k2, k3);
                    hmma_z(Sacc[1][2 * ng2],     qf[1][0], qf[1][1], qf[1][2], qf[1][3], k0, k1);
                    hmma_z(Sacc[1][2 * ng2 + 1], qf[1][0], qf[1][1], qf[1][2], qf[1][3], k2, k3);
                } else {
                    hmma(Sacc[0][2 * ng2],     qf[0][0], qf[0][1], qf[0][2], qf[0][3], k0, k1);
                    hmma(Sacc[0][2 * ng2 + 1], qf[0][0], qf[0][1], qf[0][2], qf[0][3], k2, k3);
                    hmma(Sacc[1][2 * ng2],     qf[1][0], qf[1][1], qf[1][2], qf[1][3], k0, k1);
                    hmma(Sacc[1][2 * ng2 + 1], qf[1][0], qf[1][1], qf[1][2], qf[1][3], k2, k3);
                }
            }
        }

        #pragma unroll
        for (int ks = 0; ks < 4; ks++) {
            uint32_t pa[2][4];
            #pragma unroll
            for (int mt = 0; mt < 2; mt++) {
                pa[mt][0] = ex2bf2(cvt2bf(Sacc[mt][2 * ks][1],     Sacc[mt][2 * ks][0]));
                pa[mt][1] = ex2bf2(cvt2bf(Sacc[mt][2 * ks][3],     Sacc[mt][2 * ks][2]));
                pa[mt][2] = ex2bf2(cvt2bf(Sacc[mt][2 * ks + 1][1], Sacc[mt][2 * ks + 1][0]));
                pa[mt][3] = ex2bf2(cvt2bf(Sacc[mt][2 * ks + 1][3], Sacc[mt][2 * ks + 1][2]));
            }
            #pragma unroll
            for (int ng2 = 0; ng2 < 4; ng2++) {
                uint32_t v0, v1, v2, v3;
                ldsm4(vb + ng2 * 2304 + ks * 32, v0, v1, v2, v3);
                hmma(Oacc[0][2 * ng2],     pa[0][0], pa[0][1], pa[0][2], pa[0][3], v0, v1);
                hmma(Oacc[0][2 * ng2 + 1], pa[0][0], pa[0][1], pa[0][2], pa[0][3], v2, v3);
                hmma(Oacc[1][2 * ng2],     pa[1][0], pa[1][1], pa[1][2], pa[1][3], v0, v1);
                hmma(Oacc[1][2 * ng2 + 1], pa[1][0], pa[1][1], pa[1][2], pa[1][3], v2, v3);
            }
            hmma(Racc[0], pa[0][0], pa[0][1], pa[0][2], pa[0][3], ONESBF, ONESBF);
            hmma(Racc[1], pa[1][0], pa[1][1], pa[1][2], pa[1][3], ONESBF, ONESBF);
        }
    }

    float* rsb = g_rs + (size_t)s * (CB * CH * CL) + (size_t)bh * CL + l0;
    if (tg == 0) {
        #pragma unroll
        for (int mt = 0; mt < 2; mt++) {
            rsb[w * 32 + mt * 16 + gp]     = Racc[mt][0];
            rsb[w * 32 + mt * 16 + gp + 8] = Racc[mt][2];
        }
    }

    __syncthreads();
    #pragma unroll
    for (int mt = 0; mt < 2; mt++) {
        int qb = w * 32 + mt * 16 + gp;
        #pragma unroll
        for (int n = 0; n < 8; n++) {
            int d = n * 8 + tg * 2;
            Osm[(d)     * 132 + qb]     = Oacc[mt][n][0];
            Osm[(d + 1) * 132 + qb]     = Oacc[mt][n][1];
            Osm[(d)     * 132 + qb + 8] = Oacc[mt][n][2];
            Osm[(d + 1) * 132 + qb + 8] = Oacc[mt][n][3];
        }
    }
    __syncthreads();

    float* ob = g_att + (size_t)s * (CB * CO * CL) + (size_t)bh * CC * CL + l0;
    for (int c = tid; c < 2048; c += 128) {
        int d = c >> 5, q4 = (c & 31) << 2;
        *(float4*)&ob[(size_t)d * CL + q4] = *(const float4*)&Osm[d * 132 + q4];
    }
}

// ============================================================================
// Combine: att = rna((O0 + O1) * 1/(rs0 + rs1)), in place into g_att[0].
// CMB_N threads, 2 float4 each: float4 idx = i and i + CMB_N (covers all
// 2*CMB_N = CB*CO*CL/4 float4s of slot 0).
// ============================================================================
#define CMB_N (CB * CO * CL / 8)   // 524288 threads, 2 float4 each

__global__ __launch_bounds__(256) void combine_kernel()
{
    int i = blockIdx.x * 256 + threadIdx.x;
    #pragma unroll
    for (int h = 0; h < 2; h++) {
        int lin = (i + h * CMB_N) << 2;   // element index into slot 0
        int l   = lin & (CL - 1);
        int bh  = lin >> 17;              // / (CC*CL)

        float4 o0 = *(const float4*)&g_att[lin];
        float4 o1 = *(const float4*)&g_att[CB * CO * CL + lin];
        const float* rsp = g_rs + (size_t)bh * CL + l;
        float4 r0 = *(const float4*)rsp;
        float4 r1 = *(const float4*)(rsp + CB * CH * CL);

        float4 out;
        out.x = tf32rna((o0.x + o1.x) / (r0.x + r1.x));
        out.y = tf32rna((o0.y + o1.y) / (r0.y + r1.y));
        out.z = tf32rna((o0.z + o1.z) / (r0.z + r1.z));
        out.w = tf32rna((o0.w + o1.w) / (r0.w + r1.w));
        *(float4*)&g_att[lin] = out;
    }
}

// ============================================================================
// Unify heads on tf32 HMMA; reads combined att. l-tile 32, occ 2.
// Slot: O [64 o][36 l] @0 (9216B), W [64 c][68 o] @9216 (17408B).
// ============================================================================
#define UB_STR  26624
#define U_SMEM  (3 * UB_STR)

__global__ void __launch_bounds__(256, 2) unify_kernel(
    const float* __restrict__ ub, float* __restrict__ y)
{
    extern __shared__ float usm[];
    uint32_t sbU = smem_u32(usm);

    int tid = threadIdx.x;
    int w = tid >> 5, ln = tid & 31, gp = ln >> 2, tg = ln & 3;
    int wm = w & 3, wn = w >> 2;
    int l0 = blockIdx.x * 32, b = blockIdx.y;

    auto issue = [&](int t) {
        uint32_t base = sbU + (t % 3) * UB_STR;
        const float* ag = g_att + (size_t)(b * CO + t * 64) * CL + l0;
        for (int i = tid; i < 512; i += 256) {
            int o = i >> 3, j = i & 7;
            cpa16(base + o * 144 + j * 16, ag + (size_t)o * CL + j * 4);
        }
        const float* wg = g_uwt + t * 64;
        for (int i = tid; i < 1024; i += 256) {
            int c = i >> 4, j = i & 15;
            cpa16(base + 9216 + c * 272 + j * 16, wg + (size_t)c * CO + j * 4);
        }
        CP_COMMIT();
    };

    issue(0);
    issue(1);

    float acc[2][4];
    #pragma unroll
    for (int ns = 0; ns < 2; ns++)
        #pragma unroll
        for (int r = 0; r < 4; r++) acc[ns][r] = 0.f;

    for (int t = 0; t < 8; t++) {
        if (t < 7) { CP_WAIT(1); } else { CP_WAIT(0); }
        __syncthreads();
        if (t + 2 < 8) issue(t + 2);

        const float* O0 = usm + (t % 3) * (UB_STR / 4);   // [o][36 l]
        const float* Aw = O0 + 2304;                      // [c][68 o]

        #pragma unroll
        for (int ks = 0; ks < 8; ks++) {
            int k0 = ks * 8;
            int ra = (wm * 16 + gp) * 68 + k0;
            uint32_t a0 = *(const uint32_t*)&Aw[ra + tg];
            uint32_t a1 = *(const uint32_t*)&Aw[ra + 8 * 68 + tg];
            uint32_t a2 = *(const uint32_t*)&Aw[ra + tg + 4];
            uint32_t a3 = *(const uint32_t*)&Aw[ra + 8 * 68 + tg + 4];
            int rb0 = (k0 + tg) * 36 + wn * 16 + gp;
            int rb1 = (k0 + tg + 4) * 36 + wn * 16 + gp;
            #pragma unroll
            for (int ns = 0; ns < 2; ns++) {
                uint32_t b0 = *(const uint32_t*)&O0[rb0 + ns * 8];
                uint32_t b1 = *(const uint32_t*)&O0[rb1 + ns * 8];
                tmma(acc[ns], a0, a1, a2, a3, b0, b1);
            }
        }
    }

    __syncthreads();
    float* stg = usm;   // [64 c][36 l]
    #pragma unroll
    for (int ns = 0; ns < 2; ns++) {
        int lcol = wn * 16 + ns * 8 + tg * 2;
        int c = wm * 16 + gp;
        *(float2*)&stg[(c)     * 36 + lcol] = make_float2(acc[ns][0], acc[ns][1]);
        *(float2*)&stg[(c + 8) * 36 + lcol] = make_float2(acc[ns][2], acc[ns][3]);
    }
    __syncthreads();

    for (int i = tid; i < 512; i += 256) {
        int c = i >> 3, l4 = (i & 7) << 2;
        float bb = ub[c];
        float4 v = *(const float4*)&stg[c * 36 + l4];
        v.x += bb; v.y += bb; v.z += bb; v.w += bb;
        *(float4*)&y[(size_t)(b * CC + c) * CL + l0 + l4] = v;
    }
}

// ============================================================================
extern "C" void kernel_launch(void* const* d_in, const int* in_sizes, int n_in,
                              void* d_out, int out_size)
{
    (void)in_sizes; (void)n_in; (void)out_size;
    const float* x    = (const float*)d_in[0];
    const float* q_dw = (const float*)d_in[1];
    const float* q_db = (const float*)d_in[2];
    const float* q_pw = (const float*)d_in[3];
    const float* q_pb = (const float*)d_in[4];
    const float* k_dw = (const float*)d_in[5];
    const float* k_db = (const float*)d_in[6];
    const float* k_pw = (const float*)d_in[7];
    const float* k_pb = (const float*)d_in[8];
    const float* v_dw = (const float*)d_in[9];
    const float* v_db = (const float*)d_in[10];
    const float* v_pw = (const float*)d_in[11];
    const float* v_pb = (const float*)d_in[12];
    const float* u_w  = (const float*)d_in[13];
    const float* u_b  = (const float*)d_in[14];

    cudaFuncSetAttribute(qkv_kernel,
                         cudaFuncAttributeMaxDynamicSharedMemorySize, QKV_SMEM);
    cudaFuncSetAttribute(flash_kernel,
                         cudaFuncAttributeMaxDynamicSharedMemorySize, FL_SMEM);
    cudaFuncSetAttribute(unify_kernel,
                         cudaFuncAttributeMaxDynamicSharedMemorySize, U_SMEM);

    prep_kernel<<<128, 256>>>(q_pw, k_pw, v_pw, u_w);

    qkv_kernel<<<dim3(CL / 64, CB, 3), 512, QKV_SMEM>>>(
        x, q_dw, q_db, q_pb, k_dw, k_db, k_pb, v_dw, v_db, v_pb);

    flash_kernel<<<dim3(CL / 128, CH, CB * 2), 128, FL_SMEM>>>();

    combine_kernel<<<CMB_N / 256, 256>>>();

    unify_kernel<<<dim3(CL / 32, CB), 256, U_SMEM>>>(u_b, (float*)d_out);
}